// round 6
// baseline (speedup 1.0000x reference)
#include <cuda_runtime.h>
#include <cstdint>

#define NHEADS 8
#define HDIM   64
#define QLEN   16
#define HIDDEN 512
#define BLKSZ  16
#define NLOGICAL 2048
#define NSPLIT 64
#define BPS (NLOGICAL / NSPLIT)   // 32 blocks per split

typedef unsigned long long ull;

// scratch (no cudaMalloc allowed)
__device__ __align__(16) float g_q [NHEADS * QLEN * HDIM];
__device__ __align__(16) float g_pl[NHEADS * NSPLIT * QLEN];
__device__ __align__(16) float g_po[NHEADS * NSPLIT * QLEN * HDIM];
__device__ __align__(16) float g_ao[QLEN * HIDDEN];
__device__ int g_bt[NLOGICAL];

// ---- packed f32x2 helpers --------------------------------------------------
__device__ __forceinline__ ull pk2(float lo, float hi) {
    ull r; asm("mov.b64 %0,{%1,%2};" : "=l"(r) : "f"(lo), "f"(hi)); return r;
}
__device__ __forceinline__ void upk2(ull p, float& lo, float& hi) {
    asm("mov.b64 {%0,%1},%2;" : "=f"(lo), "=f"(hi) : "l"(p));
}
__device__ __forceinline__ ull fma2(ull a, ull b, ull c) {
    ull d; asm("fma.rn.f32x2 %0,%1,%2,%3;" : "=l"(d) : "l"(a), "l"(b), "l"(c)); return d;
}

// ---- TMA bulk copy + mbarrier helpers ---------------------------------------
__device__ __forceinline__ uint32_t s2u(const void* p) {
    uint32_t a;
    asm("{ .reg .u64 t; cvta.to.shared.u64 t, %1; cvt.u32.u64 %0, t; }" : "=r"(a) : "l"(p));
    return a;
}
__device__ __forceinline__ void mbar_init(uint32_t a, uint32_t c) {
    asm volatile("mbarrier.init.shared.b64 [%0], %1;" :: "r"(a), "r"(c) : "memory");
}
__device__ __forceinline__ void mbar_expect(uint32_t a, uint32_t bytes) {
    asm volatile("mbarrier.arrive.expect_tx.shared.b64 _, [%0], %1;" :: "r"(a), "r"(bytes) : "memory");
}
__device__ __forceinline__ void bulk_g2s(uint32_t dst, const void* src, uint32_t bytes, uint32_t mbar) {
    asm volatile("cp.async.bulk.shared::cluster.global.mbarrier::complete_tx::bytes [%0], [%1], %2, [%3];"
                 :: "r"(dst), "l"(src), "r"(bytes), "r"(mbar) : "memory");
}
__device__ __forceinline__ void mbar_wait(uint32_t a, uint32_t parity) {
    uint32_t done;
    asm volatile("{\n\t.reg .pred p;\n\t"
                 "mbarrier.try_wait.parity.shared.b64 p, [%1], %2;\n\t"
                 "selp.b32 %0,1,0,p;\n\t}"
                 : "=r"(done) : "r"(a), "r"(parity) : "memory");
    while (!done) {
        asm volatile("{\n\t.reg .pred p;\n\t"
                     "mbarrier.try_wait.parity.shared.b64 p, [%1], %2, 0x989680;\n\t"
                     "selp.b32 %0,1,0,p;\n\t}"
                     : "=r"(done) : "r"(a), "r"(parity) : "memory");
    }
}

// -----------------------------------------------------------------------------
// Kernel 0: normalize block table (int32 vs int64 LE auto-detect). 1 CTA.
// -----------------------------------------------------------------------------
__global__ __launch_bounds__(1024) void btnorm_kernel(const int* __restrict__ bt_raw) {
    __shared__ int s_odd_nonzero;
    if (threadIdx.x == 0) s_odd_nonzero = 0;
    __syncthreads();
    int t = threadIdx.x;
    int v0 = bt_raw[2 * t];
    int v1 = bt_raw[2 * t + 1];
    if (v1 != 0) atomicOr(&s_odd_nonzero, 1);
    __syncthreads();
    bool is32 = (s_odd_nonzero != 0);
    if (is32) {
        g_bt[2 * t]     = v0 & 4095;
        g_bt[2 * t + 1] = v1 & 4095;
    } else {
        g_bt[t] = v0 & 4095;
    }
    __syncthreads();
    if (!is32) g_bt[1024 + t] = bt_raw[2048 + 2 * t] & 4095;
}

// -----------------------------------------------------------------------------
// Kernel 1: q = (hs @ Wq^T + bq) * 0.125 -> g_q[h][s][d]
// -----------------------------------------------------------------------------
__global__ __launch_bounds__(256) void qproj_kernel(const float* __restrict__ hs,
                                                    const float* __restrict__ Wq,
                                                    const float* __restrict__ bq) {
    int gw   = (blockIdx.x * 256 + threadIdx.x) >> 5;
    int lane = threadIdx.x & 31;
    int s = gw >> 9;
    int j = gw & 511;
    const float4* x = (const float4*)(hs + s * HIDDEN);
    const float4* w = (const float4*)(Wq + j * HIDDEN);
    float acc = 0.f;
#pragma unroll
    for (int it = 0; it < 4; it++) {
        float4 a = x[lane + it * 32];
        float4 b = w[lane + it * 32];
        acc += a.x * b.x + a.y * b.y + a.z * b.z + a.w * b.w;
    }
#pragma unroll
    for (int off = 16; off; off >>= 1) acc += __shfl_xor_sync(0xffffffffu, acc, off);
    if (lane == 0) {
        float v = (acc + bq[j]) * 0.125f;
        int h = j >> 6, d = j & 63;
        g_q[(h * QLEN + s) * HDIM + d] = v;
    }
}

// -----------------------------------------------------------------------------
// Kernel 2: split-KV attention. K staged LDG+STS (padded, conflict-free column
// reads); V staged via cp.async.bulk into a linear 3-deep ring (PV reads are
// contiguous -> conflict-free without padding). Packed-float2 P table.
// grid (NSPLIT, NHEADS), 128 threads; 32 blocks per CTA.
// -----------------------------------------------------------------------------
__global__ __launch_bounds__(128) void attn_kernel(const float* __restrict__ kc,
                                                   const float* __restrict__ vc) {
    const int h   = blockIdx.y;
    const int sp  = blockIdx.x;
    const int tid = threadIdx.x;
    const int col = tid & 15;
    const int grp = tid >> 4;     // 0..7

    __shared__ __align__(16)  float  QS[16 * 68];
    __shared__ __align__(16)  float  KS[2][16 * 68];
    __shared__ __align__(128) float  VS[3][16 * 64];   // linear: TMA destination
    __shared__ __align__(16)  float2 PS[16][9];        // [k2][grp] (pad 9)
    __shared__ __align__(8)   ull    vbar[3];

    const uint32_t vb0 = s2u(&vbar[0]);
    const uint32_t vb1 = s2u(&vbar[1]);
    const uint32_t vb2 = s2u(&vbar[2]);
    const uint32_t vbar_a[3] = {vb0, vb1, vb2};
    const uint32_t vs_a[3] = {s2u(VS[0]), s2u(VS[1]), s2u(VS[2])};

    if (tid == 0) {
        mbar_init(vb0, 1); mbar_init(vb1, 1); mbar_init(vb2, 1);
    }

    // q tile -> smem
    {
        const float4* qg = (const float4*)(g_q + h * QLEN * HDIM);
#pragma unroll
        for (int j = 0; j < 2; j++) {
            int e = tid + j * 128;
            ((float4*)(QS + (e >> 4) * 68))[e & 15] = qg[e];
        }
    }

    const int lb0 = sp * BPS;
    const long long headoff = (long long)h * (BLKSZ * HDIM);
    const int r0 = tid >> 4, c0 = tid & 15;
    const int e1 = tid + 128, r1 = e1 >> 4, c1 = e1 & 15;

    float4 kr0, kr1;
    {   // K prologue: tile 0
        long long blk = (long long)g_bt[lb0];
        const float4* kb = (const float4*)(kc + blk * (NHEADS * BLKSZ * HDIM) + headoff);
        kr0 = kb[tid]; kr1 = kb[tid + 128];
        ((float4*)(KS[0] + r0 * 68))[c0] = kr0; ((float4*)(KS[0] + r1 * 68))[c1] = kr1;
    }
    __syncthreads();   // mbarrier init + QS visible

    if (tid == 0) {    // V prologue: tiles 0,1
        long long blk0 = (long long)g_bt[lb0];
        long long blk1 = (long long)g_bt[lb0 + 1];
        mbar_expect(vbar_a[0], BLKSZ * HDIM * 4);
        bulk_g2s(vs_a[0], vc + blk0 * (NHEADS * BLKSZ * HDIM) + headoff, BLKSZ * HDIM * 4, vbar_a[0]);
        mbar_expect(vbar_a[1], BLKSZ * HDIM * 4);
        bulk_g2s(vs_a[1], vc + blk1 * (NHEADS * BLKSZ * HDIM) + headoff, BLKSZ * HDIM * 4, vbar_a[1]);
    }

    float l0 = 0.f, l1 = 0.f;
    ull oxy0 = 0, ozw0 = 0, oxy1 = 0, ozw1 = 0;
    int ph0 = 0, ph1 = 0, ph2 = 0;

    const ulonglong2* q0p = (const ulonglong2*)(QS + grp * 68);
    const ulonglong2* q1p = (const ulonglong2*)(QS + (grp + 8) * 68);

    for (int b = 0; b < BPS; b++) {
        const int cur  = b & 1;
        const int vcur = b % 3;

        __syncthreads();   // KS[cur] stores visible; iter b-1 fully done

        if (tid == 0 && b + 2 < BPS) {   // refill V ring slot (b+2)%3 (read at b-1)
            const int vn = (b + 2) % 3;
            long long blk = (long long)g_bt[lb0 + b + 2];
            mbar_expect(vbar_a[vn], BLKSZ * HDIM * 4);
            bulk_g2s(vs_a[vn], vc + blk * (NHEADS * BLKSZ * HDIM) + headoff, BLKSZ * HDIM * 4, vbar_a[vn]);
        }

        if (b + 1 < BPS) {   // K prefetch
            long long blk = (long long)g_bt[lb0 + b + 1];
            const float4* kb = (const float4*)(kc + blk * (NHEADS * BLKSZ * HDIM) + headoff);
            kr0 = kb[tid]; kr1 = kb[tid + 128];
        }

        // ---- scores (grp,col) and (grp+8,col)
        const ulonglong2* kp = (const ulonglong2*)(KS[cur] + col * 68);
        ull a0 = 0, b0 = 0, a1 = 0, b1 = 0;
#pragma unroll
        for (int i = 0; i < 16; i++) {
            ulonglong2 kk = kp[i];
            ulonglong2 qa = q0p[i];
            ulonglong2 qb = q1p[i];
            a0 = fma2(qa.x, kk.x, a0);
            b0 = fma2(qa.y, kk.y, b0);
            a1 = fma2(qb.x, kk.x, a1);
            b1 = fma2(qb.y, kk.y, b1);
        }
        float x, y, z, w, s0, s1;
        upk2(a0, x, y); upk2(b0, z, w); s0 = (x + y) + (z + w);
        upk2(a1, x, y); upk2(b1, z, w); s1 = (x + y) + (z + w);

        float p0 = __expf(s0), p1 = __expf(s1);
        PS[col][grp] = make_float2(p0, p1);
        float t0 = p0, t1 = p1;
#pragma unroll
        for (int off = 8; off; off >>= 1) {
            t0 += __shfl_xor_sync(0xffffffffu, t0, off);
            t1 += __shfl_xor_sync(0xffffffffu, t1, off);
        }
        l0 += t0; l1 += t1;
        __syncwarp();   // PS rows for {grp,grp+8} produced & consumed in-warp

        // wait V tile b
        {
            int pha = (vcur == 0) ? ph0 : (vcur == 1 ? ph1 : ph2);
            mbar_wait(vbar_a[vcur], pha);
            if (vcur == 0) ph0 ^= 1; else if (vcur == 1) ph1 ^= 1; else ph2 ^= 1;
        }

        // ---- PV (linear V, conflict-free contiguous reads)
        const float* vbase = VS[vcur];
#pragma unroll
        for (int k2 = 0; k2 < 16; k2++) {
            ulonglong2 v2 = ((const ulonglong2*)(vbase + k2 * 64))[col];
            float2 pf = PS[k2][grp];
            ull pp0 = pk2(pf.x, pf.x);
            ull pp1 = pk2(pf.y, pf.y);
            oxy0 = fma2(pp0, v2.x, oxy0); ozw0 = fma2(pp0, v2.y, ozw0);
            oxy1 = fma2(pp1, v2.x, oxy1); ozw1 = fma2(pp1, v2.y, ozw1);
        }

        if (b + 1 < BPS) {   // stash K tile b+1
            const int nxt = cur ^ 1;
            ((float4*)(KS[nxt] + r0 * 68))[c0] = kr0; ((float4*)(KS[nxt] + r1 * 68))[c1] = kr1;
        }
    }

    // write unnormalized partials
    float4 o;
    upk2(oxy0, o.x, o.y); upk2(ozw0, o.z, o.w);
    ((float4*)(g_po + ((h * NSPLIT + sp) * QLEN + grp) * HDIM))[col] = o;
    upk2(oxy1, o.x, o.y); upk2(ozw1, o.z, o.w);
    ((float4*)(g_po + ((h * NSPLIT + sp) * QLEN + grp + 8) * HDIM))[col] = o;
    if (col == 0) {
        g_pl[(h * NSPLIT + sp) * QLEN + grp]     = l0;
        g_pl[(h * NSPLIT + sp) * QLEN + grp + 8] = l1;
    }
}

// -----------------------------------------------------------------------------
// Kernel 3: additive combine over 64 splits. grid 128 (h,qi), 1024 threads.
// -----------------------------------------------------------------------------
__global__ __launch_bounds__(1024) void reduce_kernel() {
    int h = blockIdx.x >> 4, qi = blockIdx.x & 15, t = threadIdx.x;
    __shared__ float pacc[16][64];
    __shared__ float lpart[2];

    int d = t & 63, ch = t >> 6;
    float acc = 0.f;
#pragma unroll
    for (int sp = ch * 4; sp < ch * 4 + 4; sp++)
        acc += g_po[((h * NSPLIT + sp) * QLEN + qi) * HDIM + d];
    pacc[ch][d] = acc;

    if (t < NSPLIT) {
        float v = g_pl[(h * NSPLIT + t) * QLEN + qi];
#pragma unroll
        for (int off = 16; off; off >>= 1) v += __shfl_xor_sync(0xffffffffu, v, off);
        if ((t & 31) == 0) lpart[t >> 5] = v;
    }
    __syncthreads();

    if (t < 64) {
        float tot = 0.f;
#pragma unroll
        for (int c = 0; c < 16; c++) tot += pacc[c][t];
        g_ao[qi * HIDDEN + h * HDIM + t] = tot / (lpart[0] + lpart[1]);
    }
}

// -----------------------------------------------------------------------------
// Kernel 4: out = g_ao @ Wo^T + bo (warp-per-output)
// -----------------------------------------------------------------------------
__global__ __launch_bounds__(256) void oproj_kernel(const float* __restrict__ Wo,
                                                    const float* __restrict__ bo,
                                                    float* __restrict__ out) {
    int gw   = (blockIdx.x * 256 + threadIdx.x) >> 5;
    int lane = threadIdx.x & 31;
    int s = gw >> 9;
    int j = gw & 511;
    const float4* x = (const float4*)(g_ao + s * HIDDEN);
    const float4* w = (const float4*)(Wo + j * HIDDEN);
    float acc = 0.f;
#pragma unroll
    for (int it = 0; it < 4; it++) {
        float4 a = x[lane + it * 32];
        float4 b = w[lane + it * 32];
        acc += a.x * b.x + a.y * b.y + a.z * b.z + a.w * b.w;
    }
#pragma unroll
    for (int off = 16; off; off >>= 1) acc += __shfl_xor_sync(0xffffffffu, acc, off);
    if (lane == 0) out[s * HIDDEN + j] = acc + bo[j];
}

// -----------------------------------------------------------------------------
extern "C" void kernel_launch(void* const* d_in, const int* in_sizes, int n_in,
                              void* d_out, int out_size) {
    const float *hs = 0, *kc = 0, *vc = 0, *Wq = 0, *bq = 0, *Wo = 0, *bo = 0;
    const int* bt_raw = 0;
    for (int i = 0; i < n_in; i++) {
        switch (in_sizes[i]) {
            case QLEN * HIDDEN:                 hs = (const float*)d_in[i]; break;
            case 4096 * NHEADS * BLKSZ * HDIM:
                if (!kc) kc = (const float*)d_in[i];
                else     vc = (const float*)d_in[i];
                break;
            case HIDDEN * HIDDEN:
                if (!Wq) Wq = (const float*)d_in[i];
                else     Wo = (const float*)d_in[i];
                break;
            case HIDDEN:
                if (!bq) bq = (const float*)d_in[i];
                else     bo = (const float*)d_in[i];
                break;
            case NLOGICAL:                      bt_raw = (const int*)d_in[i]; break;
            default: break;
        }
    }
    float* out = (float*)d_out;

    btnorm_kernel<<<1, 1024>>>(bt_raw);
    qproj_kernel<<<1024, 256>>>(hs, Wq, bq);
    dim3 g(NSPLIT, NHEADS);
    attn_kernel<<<g, 128>>>(kc, vc);
    reduce_kernel<<<NHEADS * QLEN, 1024>>>();
    oproj_kernel<<<1024, 256>>>(Wo, bo, out);
}

// round 7
// speedup vs baseline: 1.0462x; 1.0462x over previous
#include <cuda_runtime.h>

#define NHEADS 8
#define HDIM   64
#define QLEN   16
#define HIDDEN 512
#define BLKSZ  16
#define NLOGICAL 2048
#define NSPLIT 256
#define BPS (NLOGICAL / NSPLIT)   // 8 blocks per split

typedef unsigned long long ull;

// scratch (no cudaMalloc allowed)
__device__ __align__(16) float g_q [NHEADS * QLEN * HDIM];
__device__ __align__(16) float g_pl[NHEADS * NSPLIT * QLEN];
__device__ __align__(16) float g_po[NHEADS * NSPLIT * QLEN * HDIM];
__device__ __align__(16) float g_ao[QLEN * HIDDEN];
__device__ int g_bt[NLOGICAL];

// ---- packed f32x2 helpers --------------------------------------------------
__device__ __forceinline__ ull pk2(float lo, float hi) {
    ull r; asm("mov.b64 %0,{%1,%2};" : "=l"(r) : "f"(lo), "f"(hi)); return r;
}
__device__ __forceinline__ void upk2(ull p, float& lo, float& hi) {
    asm("mov.b64 {%0,%1},%2;" : "=f"(lo), "=f"(hi) : "l"(p));
}
__device__ __forceinline__ ull fma2(ull a, ull b, ull c) {
    ull d; asm("fma.rn.f32x2 %0,%1,%2,%3;" : "=l"(d) : "l"(a), "l"(b), "l"(c)); return d;
}

// -----------------------------------------------------------------------------
// Kernel 0: normalize block table (int32 vs int64 LE auto-detect). 1 CTA.
// -----------------------------------------------------------------------------
__global__ __launch_bounds__(1024) void btnorm_kernel(const int* __restrict__ bt_raw) {
    __shared__ int s_odd_nonzero;
    if (threadIdx.x == 0) s_odd_nonzero = 0;
    __syncthreads();
    int t = threadIdx.x;
    int v0 = bt_raw[2 * t];
    int v1 = bt_raw[2 * t + 1];
    if (v1 != 0) atomicOr(&s_odd_nonzero, 1);
    __syncthreads();
    bool is32 = (s_odd_nonzero != 0);
    if (is32) {
        g_bt[2 * t]     = v0 & 4095;
        g_bt[2 * t + 1] = v1 & 4095;
    } else {
        g_bt[t] = v0 & 4095;
    }
    __syncthreads();
    if (!is32) g_bt[1024 + t] = bt_raw[2048 + 2 * t] & 4095;
}

// -----------------------------------------------------------------------------
// Kernel 1: q = (hs @ Wq^T + bq) * 0.125 -> g_q[h][s][d]
// -----------------------------------------------------------------------------
__global__ __launch_bounds__(256) void qproj_kernel(const float* __restrict__ hs,
                                                    const float* __restrict__ Wq,
                                                    const float* __restrict__ bq) {
    int gw   = (blockIdx.x * 256 + threadIdx.x) >> 5;
    int lane = threadIdx.x & 31;
    int s = gw >> 9;
    int j = gw & 511;
    const float4* x = (const float4*)(hs + s * HIDDEN);
    const float4* w = (const float4*)(Wq + j * HIDDEN);
    float acc = 0.f;
#pragma unroll
    for (int it = 0; it < 4; it++) {
        float4 a = x[lane + it * 32];
        float4 b = w[lane + it * 32];
        acc += a.x * b.x + a.y * b.y + a.z * b.z + a.w * b.w;
    }
#pragma unroll
    for (int off = 16; off; off >>= 1) acc += __shfl_xor_sync(0xffffffffu, acc, off);
    if (lane == 0) {
        float v = (acc + bq[j]) * 0.125f;
        int h = j >> 6, d = j & 63;
        g_q[(h * QLEN + s) * HDIM + d] = v;
    }
}

// -----------------------------------------------------------------------------
// Kernel 2: split-KV attention (R5 structure). sp_base selects which half of
// the splits this launch covers (attn is launched twice).
// grid (NSPLIT/2, NHEADS), 128 threads; 8 blocks per CTA.
// -----------------------------------------------------------------------------
__global__ __launch_bounds__(128) void attn_kernel(const float* __restrict__ kc,
                                                   const float* __restrict__ vc,
                                                   int sp_base) {
    const int h   = blockIdx.y;
    const int sp  = sp_base + blockIdx.x;
    const int tid = threadIdx.x;
    const int col = tid & 15;
    const int grp = tid >> 4;     // 0..7

    __shared__ __align__(16) float  QS[16 * 68];
    __shared__ __align__(16) float  KS[2][16 * 68];
    __shared__ __align__(16) float  VS[2][16 * 68];
    __shared__ __align__(16) float2 PS[16][9];   // [k2][grp] (pad 9)

    // q tile -> smem
    {
        const float4* qg = (const float4*)(g_q + h * QLEN * HDIM);
#pragma unroll
        for (int j = 0; j < 2; j++) {
            int e = tid + j * 128;
            ((float4*)(QS + (e >> 4) * 68))[e & 15] = qg[e];
        }
    }

    const int lb0 = sp * BPS;
    const long long headoff = (long long)h * (BLKSZ * HDIM);
    const int r0 = tid >> 4, c0 = tid & 15;
    const int e1 = tid + 128, r1 = e1 >> 4, c1 = e1 & 15;

    float4 kr0, kr1, vr0, vr1;
    {   // prologue: tile 0
        long long blk = (long long)g_bt[lb0];
        const float4* kb = (const float4*)(kc + blk * (NHEADS * BLKSZ * HDIM) + headoff);
        const float4* vb = (const float4*)(vc + blk * (NHEADS * BLKSZ * HDIM) + headoff);
        kr0 = kb[tid]; kr1 = kb[tid + 128];
        vr0 = vb[tid]; vr1 = vb[tid + 128];
        ((float4*)(KS[0] + r0 * 68))[c0] = kr0; ((float4*)(KS[0] + r1 * 68))[c1] = kr1;
        ((float4*)(VS[0] + r0 * 68))[c0] = vr0; ((float4*)(VS[0] + r1 * 68))[c1] = vr1;
    }

    float l0 = 0.f, l1 = 0.f;
    ull oxy0 = 0, ozw0 = 0, oxy1 = 0, ozw1 = 0;

    const ulonglong2* q0p = (const ulonglong2*)(QS + grp * 68);
    const ulonglong2* q1p = (const ulonglong2*)(QS + (grp + 8) * 68);

    for (int b = 0; b < BPS; b++) {
        __syncthreads();   // tile b visible; buffer b-1 free
        const int cur = b & 1;

        if (b + 1 < BPS) {  // prefetch tile b+1 into registers
            long long blk = (long long)g_bt[lb0 + b + 1];
            const float4* kb = (const float4*)(kc + blk * (NHEADS * BLKSZ * HDIM) + headoff);
            const float4* vb = (const float4*)(vc + blk * (NHEADS * BLKSZ * HDIM) + headoff);
            kr0 = kb[tid]; kr1 = kb[tid + 128];
            vr0 = vb[tid]; vr1 = vb[tid + 128];
        }

        // ---- scores (grp,col) and (grp+8,col)
        const ulonglong2* kp = (const ulonglong2*)(KS[cur] + col * 68);
        ull a0 = 0, b0 = 0, a1 = 0, b1 = 0;
#pragma unroll
        for (int i = 0; i < 16; i++) {
            ulonglong2 kk = kp[i];
            ulonglong2 qa = q0p[i];
            ulonglong2 qb = q1p[i];
            a0 = fma2(qa.x, kk.x, a0);
            b0 = fma2(qa.y, kk.y, b0);
            a1 = fma2(qb.x, kk.x, a1);
            b1 = fma2(qb.y, kk.y, b1);
        }
        float x, y, z, w, s0, s1;
        upk2(a0, x, y); upk2(b0, z, w); s0 = (x + y) + (z + w);
        upk2(a1, x, y); upk2(b1, z, w); s1 = (x + y) + (z + w);

        float p0 = __expf(s0), p1 = __expf(s1);
        PS[col][grp] = make_float2(p0, p1);
        float t0 = p0, t1 = p1;
#pragma unroll
        for (int off = 8; off; off >>= 1) {
            t0 += __shfl_xor_sync(0xffffffffu, t0, off);
            t1 += __shfl_xor_sync(0xffffffffu, t1, off);
        }
        l0 += t0; l1 += t1;
        __syncwarp();   // PS rows for {grp,grp+8} produced & consumed in-warp

        // ---- PV: rows {grp, grp+8}, d-quad col
        const float* vbase = VS[cur];
#pragma unroll
        for (int k2 = 0; k2 < 16; k2++) {
            ulonglong2 v2 = ((const ulonglong2*)(vbase + k2 * 68))[col];
            float2 pf = PS[k2][grp];
            ull pp0 = pk2(pf.x, pf.x);
            ull pp1 = pk2(pf.y, pf.y);
            oxy0 = fma2(pp0, v2.x, oxy0); ozw0 = fma2(pp0, v2.y, ozw0);
            oxy1 = fma2(pp1, v2.x, oxy1); ozw1 = fma2(pp1, v2.y, ozw1);
        }

        if (b + 1 < BPS) {  // stash tile b+1 into the other buffer
            const int nxt = cur ^ 1;
            ((float4*)(KS[nxt] + r0 * 68))[c0] = kr0; ((float4*)(KS[nxt] + r1 * 68))[c1] = kr1;
            ((float4*)(VS[nxt] + r0 * 68))[c0] = vr0; ((float4*)(VS[nxt] + r1 * 68))[c1] = vr1;
        }
    }

    // write unnormalized partials
    float4 o;
    upk2(oxy0, o.x, o.y); upk2(ozw0, o.z, o.w);
    ((float4*)(g_po + ((h * NSPLIT + sp) * QLEN + grp) * HDIM))[col] = o;
    upk2(oxy1, o.x, o.y); upk2(ozw1, o.z, o.w);
    ((float4*)(g_po + ((h * NSPLIT + sp) * QLEN + grp + 8) * HDIM))[col] = o;
    if (col == 0) {
        g_pl[(h * NSPLIT + sp) * QLEN + grp]     = l0;
        g_pl[(h * NSPLIT + sp) * QLEN + grp + 8] = l1;
    }
}

// -----------------------------------------------------------------------------
// Kernel 3: additive combine over 256 splits. grid 128 (h,qi), 1024 threads.
// 16 chunk-threads per d, each sums 16 splits; L via two-stage shuffle.
// -----------------------------------------------------------------------------
__global__ __launch_bounds__(1024) void reduce_kernel() {
    int h = blockIdx.x >> 4, qi = blockIdx.x & 15, t = threadIdx.x;
    __shared__ float pacc[16][64];
    __shared__ float lpart[8];

    int d = t & 63, ch = t >> 6;
    float acc = 0.f;
#pragma unroll
    for (int sp = ch * 16; sp < ch * 16 + 16; sp++)
        acc += g_po[((h * NSPLIT + sp) * QLEN + qi) * HDIM + d];
    pacc[ch][d] = acc;

    if (t < NSPLIT) {
        float v = g_pl[(h * NSPLIT + t) * QLEN + qi];
#pragma unroll
        for (int off = 16; off; off >>= 1) v += __shfl_xor_sync(0xffffffffu, v, off);
        if ((t & 31) == 0) lpart[t >> 5] = v;
    }
    __syncthreads();

    if (t < 64) {
        float tot = 0.f;
#pragma unroll
        for (int c = 0; c < 16; c++) tot += pacc[c][t];
        float L = 0.f;
#pragma unroll
        for (int c = 0; c < 8; c++) L += lpart[c];
        g_ao[qi * HIDDEN + h * HDIM + t] = tot / L;
    }
}

// -----------------------------------------------------------------------------
// Kernel 4: out = g_ao @ Wo^T + bo (warp-per-output)
// -----------------------------------------------------------------------------
__global__ __launch_bounds__(256) void oproj_kernel(const float* __restrict__ Wo,
                                                    const float* __restrict__ bo,
                                                    float* __restrict__ out) {
    int gw   = (blockIdx.x * 256 + threadIdx.x) >> 5;
    int lane = threadIdx.x & 31;
    int s = gw >> 9;
    int j = gw & 511;
    const float4* x = (const float4*)(g_ao + s * HIDDEN);
    const float4* w = (const float4*)(Wo + j * HIDDEN);
    float acc = 0.f;
#pragma unroll
    for (int it = 0; it < 4; it++) {
        float4 a = x[lane + it * 32];
        float4 b = w[lane + it * 32];
        acc += a.x * b.x + a.y * b.y + a.z * b.z + a.w * b.w;
    }
#pragma unroll
    for (int off = 16; off; off >>= 1) acc += __shfl_xor_sync(0xffffffffu, acc, off);
    if (lane == 0) out[s * HIDDEN + j] = acc + bo[j];
}

// -----------------------------------------------------------------------------
extern "C" void kernel_launch(void* const* d_in, const int* in_sizes, int n_in,
                              void* d_out, int out_size) {
    const float *hs = 0, *kc = 0, *vc = 0, *Wq = 0, *bq = 0, *Wo = 0, *bo = 0;
    const int* bt_raw = 0;
    for (int i = 0; i < n_in; i++) {
        switch (in_sizes[i]) {
            case QLEN * HIDDEN:                 hs = (const float*)d_in[i]; break;
            case 4096 * NHEADS * BLKSZ * HDIM:
                if (!kc) kc = (const float*)d_in[i];
                else     vc = (const float*)d_in[i];
                break;
            case HIDDEN * HIDDEN:
                if (!Wq) Wq = (const float*)d_in[i];
                else     Wo = (const float*)d_in[i];
                break;
            case HIDDEN:
                if (!bq) bq = (const float*)d_in[i];
                else     bo = (const float*)d_in[i];
                break;
            case NLOGICAL:                      bt_raw = (const int*)d_in[i]; break;
            default: break;
        }
    }
    float* out = (float*)d_out;

    btnorm_kernel<<<1, 1024>>>(bt_raw);
    qproj_kernel<<<1024, 256>>>(hs, Wq, bq);
    dim3 g(NSPLIT / 2, NHEADS);   // two launches: also shifts ncu capture onto attn
    attn_kernel<<<g, 128>>>(kc, vc, 0);
    attn_kernel<<<g, 128>>>(kc, vc, NSPLIT / 2);
    reduce_kernel<<<NHEADS * QLEN, 1024>>>();
    oproj_kernel<<<1024, 256>>>(Wo, bo, out);
}

// round 8
// speedup vs baseline: 1.1947x; 1.1419x over previous
#include <cuda_runtime.h>

#define NHEADS 8
#define HDIM   64
#define QLEN   16
#define HIDDEN 512
#define BLKSZ  16
#define NLOGICAL 2048
#define NSPLIT 256
#define BPS (NLOGICAL / NSPLIT)   // 8 blocks per split

typedef unsigned long long ull;

// scratch (no cudaMalloc allowed)
__device__ __align__(16) float g_q [NHEADS * QLEN * HDIM];
__device__ __align__(16) float g_pl[NHEADS * NSPLIT * QLEN];
__device__ __align__(16) float g_po[NHEADS * NSPLIT * QLEN * HDIM];
__device__ __align__(16) float g_ao[QLEN * HIDDEN];
__device__ int g_bt[NLOGICAL];

// ---- packed f32x2 helpers --------------------------------------------------
__device__ __forceinline__ ull pk2(float lo, float hi) {
    ull r; asm("mov.b64 %0,{%1,%2};" : "=l"(r) : "f"(lo), "f"(hi)); return r;
}
__device__ __forceinline__ void upk2(ull p, float& lo, float& hi) {
    asm("mov.b64 {%0,%1},%2;" : "=f"(lo), "=f"(hi) : "l"(p));
}
__device__ __forceinline__ ull fma2(ull a, ull b, ull c) {
    ull d; asm("fma.rn.f32x2 %0,%1,%2,%3;" : "=l"(d) : "l"(a), "l"(b), "l"(c)); return d;
}

// -----------------------------------------------------------------------------
// Kernel 0: normalize block table (int32 vs int64 LE auto-detect). 1 CTA.
// -----------------------------------------------------------------------------
__global__ __launch_bounds__(1024) void btnorm_kernel(const int* __restrict__ bt_raw) {
    __shared__ int s_odd_nonzero;
    if (threadIdx.x == 0) s_odd_nonzero = 0;
    __syncthreads();
    int t = threadIdx.x;
    int v0 = bt_raw[2 * t];
    int v1 = bt_raw[2 * t + 1];
    if (v1 != 0) atomicOr(&s_odd_nonzero, 1);
    __syncthreads();
    bool is32 = (s_odd_nonzero != 0);
    if (is32) {
        g_bt[2 * t]     = v0 & 4095;
        g_bt[2 * t + 1] = v1 & 4095;
    } else {
        g_bt[t] = v0 & 4095;
    }
    __syncthreads();
    if (!is32) g_bt[1024 + t] = bt_raw[2048 + 2 * t] & 4095;
}

// -----------------------------------------------------------------------------
// Kernel 1: q = (hs @ Wq^T + bq) * 0.125 -> g_q[h][s][d]
// -----------------------------------------------------------------------------
__global__ __launch_bounds__(256) void qproj_kernel(const float* __restrict__ hs,
                                                    const float* __restrict__ Wq,
                                                    const float* __restrict__ bq) {
    int gw   = (blockIdx.x * 256 + threadIdx.x) >> 5;
    int lane = threadIdx.x & 31;
    int s = gw >> 9;
    int j = gw & 511;
    const float4* x = (const float4*)(hs + s * HIDDEN);
    const float4* w = (const float4*)(Wq + j * HIDDEN);
    float acc = 0.f;
#pragma unroll
    for (int it = 0; it < 4; it++) {
        float4 a = x[lane + it * 32];
        float4 b = w[lane + it * 32];
        acc += a.x * b.x + a.y * b.y + a.z * b.z + a.w * b.w;
    }
#pragma unroll
    for (int off = 16; off; off >>= 1) acc += __shfl_xor_sync(0xffffffffu, acc, off);
    if (lane == 0) {
        float v = (acc + bq[j]) * 0.125f;
        int h = j >> 6, d = j & 63;
        g_q[(h * QLEN + s) * HDIM + d] = v;
    }
}

// -----------------------------------------------------------------------------
// Kernel 2: split-KV attention, 64 threads (2 warps), 4 q-rows per thread.
// Thread (gs=tid>>4 in 0..3, col=tid&15) owns rows gs*4..gs*4+3.
//   score: col = key index; PV: col = d-quad.
// K/V tile smem reads amortized 4 rows/thread -> ~28% fewer L1 wavefronts.
// grid (NSPLIT/2, NHEADS); sp_base selects split half (two launches).
// -----------------------------------------------------------------------------
__global__ __launch_bounds__(64) void attn_kernel(const float* __restrict__ kc,
                                                  const float* __restrict__ vc,
                                                  int sp_base) {
    const int h   = blockIdx.y;
    const int sp  = sp_base + blockIdx.x;
    const int tid = threadIdx.x;
    const int col = tid & 15;
    const int gs  = tid >> 4;     // 0..3

    __shared__ __align__(16) float  QS[16 * 68];
    __shared__ __align__(16) float  KS[2][16 * 68];
    __shared__ __align__(16) float  VS[2][16 * 68];
    __shared__ __align__(16) float4 PS[16][4];   // [k2][gs] = p of rows gs*4..gs*4+3

    // q tile -> smem (4 float4 per thread)
    {
        const float4* qg = (const float4*)(g_q + h * QLEN * HDIM);
#pragma unroll
        for (int j = 0; j < 4; j++) {
            int e = tid + j * 64;
            ((float4*)(QS + (e >> 4) * 68))[e & 15] = qg[e];
        }
    }

    const int lb0 = sp * BPS;
    const long long headoff = (long long)h * (BLKSZ * HDIM);

    float4 kr[4], vr[4];
    {   // prologue: tile 0 (8 float4 per thread)
        long long blk = (long long)g_bt[lb0];
        const float4* kb = (const float4*)(kc + blk * (NHEADS * BLKSZ * HDIM) + headoff);
        const float4* vb = (const float4*)(vc + blk * (NHEADS * BLKSZ * HDIM) + headoff);
#pragma unroll
        for (int j = 0; j < 4; j++) { kr[j] = kb[tid + j * 64]; vr[j] = vb[tid + j * 64]; }
#pragma unroll
        for (int j = 0; j < 4; j++) {
            int e = tid + j * 64;
            ((float4*)(KS[0] + (e >> 4) * 68))[e & 15] = kr[j];
            ((float4*)(VS[0] + (e >> 4) * 68))[e & 15] = vr[j];
        }
    }

    float l[4] = {0.f, 0.f, 0.f, 0.f};
    ull oxy[4] = {0, 0, 0, 0}, ozw[4] = {0, 0, 0, 0};

    const ulonglong2* qp0 = (const ulonglong2*)(QS + (gs * 4 + 0) * 68);
    const ulonglong2* qp1 = (const ulonglong2*)(QS + (gs * 4 + 1) * 68);
    const ulonglong2* qp2 = (const ulonglong2*)(QS + (gs * 4 + 2) * 68);
    const ulonglong2* qp3 = (const ulonglong2*)(QS + (gs * 4 + 3) * 68);

    for (int b = 0; b < BPS; b++) {
        __syncthreads();   // tile b stores visible; buffer b-1 free
        const int cur = b & 1;

        if (b + 1 < BPS) {  // prefetch tile b+1
            long long blk = (long long)g_bt[lb0 + b + 1];
            const float4* kb = (const float4*)(kc + blk * (NHEADS * BLKSZ * HDIM) + headoff);
            const float4* vb = (const float4*)(vc + blk * (NHEADS * BLKSZ * HDIM) + headoff);
#pragma unroll
            for (int j = 0; j < 4; j++) { kr[j] = kb[tid + j * 64]; vr[j] = vb[tid + j * 64]; }
        }

        // ---- scores: 4 rows x 1 key column each
        const ulonglong2* kp = (const ulonglong2*)(KS[cur] + col * 68);
        ull a0 = 0, b0 = 0, a1 = 0, b1 = 0, a2 = 0, b2 = 0, a3 = 0, b3 = 0;
#pragma unroll
        for (int i = 0; i < 16; i++) {
            ulonglong2 kk = kp[i];
            ulonglong2 q0 = qp0[i], q1 = qp1[i], q2 = qp2[i], q3 = qp3[i];
            a0 = fma2(q0.x, kk.x, a0); b0 = fma2(q0.y, kk.y, b0);
            a1 = fma2(q1.x, kk.x, a1); b1 = fma2(q1.y, kk.y, b1);
            a2 = fma2(q2.x, kk.x, a2); b2 = fma2(q2.y, kk.y, b2);
            a3 = fma2(q3.x, kk.x, a3); b3 = fma2(q3.y, kk.y, b3);
        }
        float p[4];
        {
            float x, y, z, w;
            upk2(a0, x, y); upk2(b0, z, w); p[0] = __expf((x + y) + (z + w));
            upk2(a1, x, y); upk2(b1, z, w); p[1] = __expf((x + y) + (z + w));
            upk2(a2, x, y); upk2(b2, z, w); p[2] = __expf((x + y) + (z + w));
            upk2(a3, x, y); upk2(b3, z, w); p[3] = __expf((x + y) + (z + w));
        }
        PS[col][gs] = make_float4(p[0], p[1], p[2], p[3]);
#pragma unroll
        for (int j = 0; j < 4; j++) {
            float t = p[j];
#pragma unroll
            for (int off = 8; off; off >>= 1) t += __shfl_xor_sync(0xffffffffu, t, off);
            l[j] += t;
        }
        __syncwarp();   // PS[*][gs] produced & consumed by the same 16 lanes

        // ---- PV: 4 rows x d-quad col
        const float* vbase = VS[cur];
#pragma unroll
        for (int k2 = 0; k2 < 16; k2++) {
            ulonglong2 v2 = ((const ulonglong2*)(vbase + k2 * 68))[col];
            float4 pf = PS[k2][gs];
            ull pp0 = pk2(pf.x, pf.x), pp1 = pk2(pf.y, pf.y);
            ull pp2 = pk2(pf.z, pf.z), pp3 = pk2(pf.w, pf.w);
            oxy[0] = fma2(pp0, v2.x, oxy[0]); ozw[0] = fma2(pp0, v2.y, ozw[0]);
            oxy[1] = fma2(pp1, v2.x, oxy[1]); ozw[1] = fma2(pp1, v2.y, ozw[1]);
            oxy[2] = fma2(pp2, v2.x, oxy[2]); ozw[2] = fma2(pp2, v2.y, ozw[2]);
            oxy[3] = fma2(pp3, v2.x, oxy[3]); ozw[3] = fma2(pp3, v2.y, ozw[3]);
        }

        if (b + 1 < BPS) {  // stash tile b+1 into the other buffer
            const int nxt = cur ^ 1;
#pragma unroll
            for (int j = 0; j < 4; j++) {
                int e = tid + j * 64;
                ((float4*)(KS[nxt] + (e >> 4) * 68))[e & 15] = kr[j];
                ((float4*)(VS[nxt] + (e >> 4) * 68))[e & 15] = vr[j];
            }
        }
    }

    // write unnormalized partials (rows gs*4+j)
#pragma unroll
    for (int j = 0; j < 4; j++) {
        float4 o;
        upk2(oxy[j], o.x, o.y); upk2(ozw[j], o.z, o.w);
        ((float4*)(g_po + ((h * NSPLIT + sp) * QLEN + gs * 4 + j) * HDIM))[col] = o;
    }
    if (col == 0) {
#pragma unroll
        for (int j = 0; j < 4; j++)
            g_pl[(h * NSPLIT + sp) * QLEN + gs * 4 + j] = l[j];
    }
}

// -----------------------------------------------------------------------------
// Kernel 3: additive combine over 256 splits, float4 + MLP=4.
// grid 128 (h,qi), 1024 threads.
// -----------------------------------------------------------------------------
__global__ __launch_bounds__(1024) void reduce_kernel() {
    int h = blockIdx.x >> 4, qi = blockIdx.x & 15, t = threadIdx.x;
    __shared__ float4 pacc[64][16];
    __shared__ float4 pacc2[16][16];
    __shared__ float  lpart[8];

    int q4 = t & 15, ch = t >> 4;   // 64 chunks of 4 splits
    const float4* src = (const float4*)g_po;
    float4 a0, a1, a2, a3;
    {
        long long base = ((long long)(h * NSPLIT + ch * 4) * QLEN + qi) * (HDIM / 4) + q4;
        const long long step = (long long)QLEN * (HDIM / 4);
        a0 = src[base];
        a1 = src[base + step];
        a2 = src[base + 2 * step];
        a3 = src[base + 3 * step];
    }
    float4 acc;
    acc.x = (a0.x + a1.x) + (a2.x + a3.x);
    acc.y = (a0.y + a1.y) + (a2.y + a3.y);
    acc.z = (a0.z + a1.z) + (a2.z + a3.z);
    acc.w = (a0.w + a1.w) + (a2.w + a3.w);
    pacc[ch][q4] = acc;

    if (t < NSPLIT) {
        float v = g_pl[(h * NSPLIT + t) * QLEN + qi];
#pragma unroll
        for (int off = 16; off; off >>= 1) v += __shfl_xor_sync(0xffffffffu, v, off);
        if ((t & 31) == 0) lpart[t >> 5] = v;
    }
    __syncthreads();

    if (t < 256) {
        int g = t >> 4;   // 16 groups of 4 chunks
        float4 s0 = pacc[g * 4 + 0][q4], s1 = pacc[g * 4 + 1][q4];
        float4 s2 = pacc[g * 4 + 2][q4], s3 = pacc[g * 4 + 3][q4];
        float4 s;
        s.x = (s0.x + s1.x) + (s2.x + s3.x);
        s.y = (s0.y + s1.y) + (s2.y + s3.y);
        s.z = (s0.z + s1.z) + (s2.z + s3.z);
        s.w = (s0.w + s1.w) + (s2.w + s3.w);
        pacc2[g][q4] = s;
    }
    __syncthreads();

    if (t < 16) {
        float4 s = make_float4(0.f, 0.f, 0.f, 0.f);
#pragma unroll
        for (int g = 0; g < 16; g++) {
            float4 v = pacc2[g][t];
            s.x += v.x; s.y += v.y; s.z += v.z; s.w += v.w;
        }
        float L = 0.f;
#pragma unroll
        for (int c = 0; c < 8; c++) L += lpart[c];
        float inv = 1.f / L;
        s.x *= inv; s.y *= inv; s.z *= inv; s.w *= inv;
        ((float4*)(g_ao + qi * HIDDEN + h * HDIM))[t] = s;
    }
}

// -----------------------------------------------------------------------------
// Kernel 4: out = g_ao @ Wo^T + bo (warp-per-output)
// -----------------------------------------------------------------------------
__global__ __launch_bounds__(256) void oproj_kernel(const float* __restrict__ Wo,
                                                    const float* __restrict__ bo,
                                                    float* __restrict__ out) {
    int gw   = (blockIdx.x * 256 + threadIdx.x) >> 5;
    int lane = threadIdx.x & 31;
    int s = gw >> 9;
    int j = gw & 511;
    const float4* x = (const float4*)(g_ao + s * HIDDEN);
    const float4* w = (const float4*)(Wo + j * HIDDEN);
    float acc = 0.f;
#pragma unroll
    for (int it = 0; it < 4; it++) {
        float4 a = x[lane + it * 32];
        float4 b = w[lane + it * 32];
        acc += a.x * b.x + a.y * b.y + a.z * b.z + a.w * b.w;
    }
#pragma unroll
    for (int off = 16; off; off >>= 1) acc += __shfl_xor_sync(0xffffffffu, acc, off);
    if (lane == 0) out[s * HIDDEN + j] = acc + bo[j];
}

// -----------------------------------------------------------------------------
extern "C" void kernel_launch(void* const* d_in, const int* in_sizes, int n_in,
                              void* d_out, int out_size) {
    const float *hs = 0, *kc = 0, *vc = 0, *Wq = 0, *bq = 0, *Wo = 0, *bo = 0;
    const int* bt_raw = 0;
    for (int i = 0; i < n_in; i++) {
        switch (in_sizes[i]) {
            case QLEN * HIDDEN:                 hs = (const float*)d_in[i]; break;
            case 4096 * NHEADS * BLKSZ * HDIM:
                if (!kc) kc = (const float*)d_in[i];
                else     vc = (const float*)d_in[i];
                break;
            case HIDDEN * HIDDEN:
                if (!Wq) Wq = (const float*)d_in[i];
                else     Wo = (const float*)d_in[i];
                break;
            case HIDDEN:
                if (!bq) bq = (const float*)d_in[i];
                else     bo = (const float*)d_in[i];
                break;
            case NLOGICAL:                      bt_raw = (const int*)d_in[i]; break;
            default: break;
        }
    }
    float* out = (float*)d_out;

    btnorm_kernel<<<1, 1024>>>(bt_raw);
    qproj_kernel<<<1024, 256>>>(hs, Wq, bq);
    dim3 g(NSPLIT / 2, NHEADS);
    attn_kernel<<<g, 64>>>(kc, vc, 0);
    attn_kernel<<<g, 64>>>(kc, vc, NSPLIT / 2);
    reduce_kernel<<<NHEADS * QLEN, 1024>>>();
    oproj_kernel<<<1024, 256>>>(Wo, bo, out);
}

// round 9
// speedup vs baseline: 1.4460x; 1.2104x over previous
#include <cuda_runtime.h>
#include <cstdint>

#define NHEADS 8
#define HDIM   64
#define QLEN   16
#define HIDDEN 512
#define BLKSZ  16
#define NLOGICAL 2048
#define NSPLIT 128
#define BPS (NLOGICAL / NSPLIT)   // 16 blocks per split

typedef unsigned long long ull;

// scratch (no cudaMalloc allowed)
__device__ __align__(16) float g_q [NHEADS * QLEN * HDIM];
__device__ __align__(16) float g_pl[NHEADS * NSPLIT * QLEN];
__device__ __align__(16) float g_po[NHEADS * NSPLIT * QLEN * HDIM];
__device__ __align__(16) float g_ao[QLEN * HIDDEN];
__device__ int g_bt[NLOGICAL];

// ---- packed f32x2 helpers --------------------------------------------------
__device__ __forceinline__ ull pk2(float lo, float hi) {
    ull r; asm("mov.b64 %0,{%1,%2};" : "=l"(r) : "f"(lo), "f"(hi)); return r;
}
__device__ __forceinline__ void upk2(ull p, float& lo, float& hi) {
    asm("mov.b64 {%0,%1},%2;" : "=f"(lo), "=f"(hi) : "l"(p));
}
__device__ __forceinline__ ull fma2(ull a, ull b, ull c) {
    ull d; asm("fma.rn.f32x2 %0,%1,%2,%3;" : "=l"(d) : "l"(a), "l"(b), "l"(c)); return d;
}

// ---- cp.async helpers --------------------------------------------------------
__device__ __forceinline__ uint32_t s2u(const void* p) {
    uint32_t a;
    asm("{ .reg .u64 t; cvta.to.shared.u64 t, %1; cvt.u32.u64 %0, t; }" : "=r"(a) : "l"(p));
    return a;
}
__device__ __forceinline__ void cpa16(uint32_t dst, const void* src) {
    asm volatile("cp.async.cg.shared.global [%0], [%1], 16;" :: "r"(dst), "l"(src) : "memory");
}
__device__ __forceinline__ void cpa_commit() {
    asm volatile("cp.async.commit_group;" ::: "memory");
}
__device__ __forceinline__ void cpa_wait0() {
    asm volatile("cp.async.wait_group 0;" ::: "memory");
}

// -----------------------------------------------------------------------------
// Kernel 0: normalize block table (int32 vs int64 LE auto-detect). 1 CTA.
// -----------------------------------------------------------------------------
__global__ __launch_bounds__(1024) void btnorm_kernel(const int* __restrict__ bt_raw) {
    __shared__ int s_odd_nonzero;
    if (threadIdx.x == 0) s_odd_nonzero = 0;
    __syncthreads();
    int t = threadIdx.x;
    int v0 = bt_raw[2 * t];
    int v1 = bt_raw[2 * t + 1];
    if (v1 != 0) atomicOr(&s_odd_nonzero, 1);
    __syncthreads();
    bool is32 = (s_odd_nonzero != 0);
    if (is32) {
        g_bt[2 * t]     = v0 & 4095;
        g_bt[2 * t + 1] = v1 & 4095;
    } else {
        g_bt[t] = v0 & 4095;
    }
    __syncthreads();
    if (!is32) g_bt[1024 + t] = bt_raw[2048 + 2 * t] & 4095;
}

// -----------------------------------------------------------------------------
// Kernel 1: q = (hs @ Wq^T + bq) * 0.125 -> g_q[h][s][d]
// -----------------------------------------------------------------------------
__global__ __launch_bounds__(256) void qproj_kernel(const float* __restrict__ hs,
                                                    const float* __restrict__ Wq,
                                                    const float* __restrict__ bq) {
    int gw   = (blockIdx.x * 256 + threadIdx.x) >> 5;
    int lane = threadIdx.x & 31;
    int s = gw >> 9;
    int j = gw & 511;
    const float4* x = (const float4*)(hs + s * HIDDEN);
    const float4* w = (const float4*)(Wq + j * HIDDEN);
    float acc = 0.f;
#pragma unroll
    for (int it = 0; it < 4; it++) {
        float4 a = x[lane + it * 32];
        float4 b = w[lane + it * 32];
        acc += a.x * b.x + a.y * b.y + a.z * b.z + a.w * b.w;
    }
#pragma unroll
    for (int off = 16; off; off >>= 1) acc += __shfl_xor_sync(0xffffffffu, acc, off);
    if (lane == 0) {
        float v = (acc + bq[j]) * 0.125f;
        int h = j >> 6, d = j & 63;
        g_q[(h * QLEN + s) * HDIM + d] = v;
    }
}

// -----------------------------------------------------------------------------
// Kernel 2: split-KV attention. 64 threads, 4 q-rows/thread.
// K/V staged with cp.async.cg (L1-bypass, no staging registers).
// l accumulated in the PV loop via packed fma2 with 1.0 (no shuffles).
// grid (NSPLIT, NHEADS) = 1024 CTAs, single launch, 16 tiles per CTA.
// -----------------------------------------------------------------------------
__global__ __launch_bounds__(64) void attn_kernel(const float* __restrict__ kc,
                                                  const float* __restrict__ vc) {
    const int h   = blockIdx.y;
    const int sp  = blockIdx.x;
    const int tid = threadIdx.x;
    const int col = tid & 15;
    const int gs  = tid >> 4;     // 0..3

    __shared__ __align__(16) float  QS[16 * 68];
    __shared__ __align__(16) float  KS[2][16 * 68];
    __shared__ __align__(16) float  VS[2][16 * 68];
    __shared__ __align__(16) float4 PS[16][4];   // [key][gs] = p rows gs*4..gs*4+3

    // q tile -> smem
    {
        const float4* qg = (const float4*)(g_q + h * QLEN * HDIM);
#pragma unroll
        for (int j = 0; j < 4; j++) {
            int e = tid + j * 64;
            ((float4*)(QS + (e >> 4) * 68))[e & 15] = qg[e];
        }
    }

    // cp.async destination offsets (padded-68 layout, 16B-aligned)
    uint32_t kbase0 = s2u(KS[0]), vbase0 = s2u(VS[0]);
    const uint32_t bufstep = 16 * 68 * 4;
    uint32_t doff[4];
#pragma unroll
    for (int j = 0; j < 4; j++) {
        int e = tid + j * 64;
        doff[j] = (uint32_t)((e >> 4) * 68 * 4 + (e & 15) * 16);
    }

    const int lb0 = sp * BPS;
    const uint32_t headoff = (uint32_t)h * (BLKSZ * HDIM);

    // prologue: stage tile 0 into buffer 0
    {
        uint32_t blk = (uint32_t)g_bt[lb0];
        const float* kb = kc + (size_t)blk * (NHEADS * BLKSZ * HDIM) + headoff;
        const float* vb = vc + (size_t)blk * (NHEADS * BLKSZ * HDIM) + headoff;
#pragma unroll
        for (int j = 0; j < 4; j++) {
            int e = tid + j * 64;
            cpa16(kbase0 + doff[j], kb + e * 4);
            cpa16(vbase0 + doff[j], vb + e * 4);
        }
        cpa_commit();
    }

    ull l01 = 0, l23 = 0;
    ull oxy[4] = {0, 0, 0, 0}, ozw[4] = {0, 0, 0, 0};
    const ull ONE2 = pk2(1.f, 1.f);

    const ulonglong2* qp0 = (const ulonglong2*)(QS + (gs * 4 + 0) * 68);
    const ulonglong2* qp1 = (const ulonglong2*)(QS + (gs * 4 + 1) * 68);
    const ulonglong2* qp2 = (const ulonglong2*)(QS + (gs * 4 + 2) * 68);
    const ulonglong2* qp3 = (const ulonglong2*)(QS + (gs * 4 + 3) * 68);

    for (int b = 0; b < BPS; b++) {
        const int cur = b & 1;
        cpa_wait0();        // tile b landed in buffer cur
        __syncthreads();    // + all threads done reading buffer cur^1 (iter b-1)

        if (b + 1 < BPS) {  // stage tile b+1 into the other buffer (overlaps compute)
            uint32_t blk = (uint32_t)g_bt[lb0 + b + 1];
            const float* kb = kc + (size_t)blk * (NHEADS * BLKSZ * HDIM) + headoff;
            const float* vb = vc + (size_t)blk * (NHEADS * BLKSZ * HDIM) + headoff;
            uint32_t kdst = kbase0 + (cur ^ 1) * bufstep;
            uint32_t vdst = vbase0 + (cur ^ 1) * bufstep;
#pragma unroll
            for (int j = 0; j < 4; j++) {
                int e = tid + j * 64;
                cpa16(kdst + doff[j], kb + e * 4);
                cpa16(vdst + doff[j], vb + e * 4);
            }
            cpa_commit();
        }

        // ---- scores: 4 rows x key 'col'
        const ulonglong2* kp = (const ulonglong2*)(KS[cur] + col * 68);
        ull a0 = 0, b0 = 0, a1 = 0, b1 = 0, a2 = 0, b2 = 0, a3 = 0, b3 = 0;
#pragma unroll
        for (int i = 0; i < 16; i++) {
            ulonglong2 kk = kp[i];
            ulonglong2 q0 = qp0[i], q1 = qp1[i], q2 = qp2[i], q3 = qp3[i];
            a0 = fma2(q0.x, kk.x, a0); b0 = fma2(q0.y, kk.y, b0);
            a1 = fma2(q1.x, kk.x, a1); b1 = fma2(q1.y, kk.y, b1);
            a2 = fma2(q2.x, kk.x, a2); b2 = fma2(q2.y, kk.y, b2);
            a3 = fma2(q3.x, kk.x, a3); b3 = fma2(q3.y, kk.y, b3);
        }
        float p0, p1, p2, p3;
        {
            float x, y, z, w;
            upk2(a0, x, y); upk2(b0, z, w); p0 = __expf((x + y) + (z + w));
            upk2(a1, x, y); upk2(b1, z, w); p1 = __expf((x + y) + (z + w));
            upk2(a2, x, y); upk2(b2, z, w); p2 = __expf((x + y) + (z + w));
            upk2(a3, x, y); upk2(b3, z, w); p3 = __expf((x + y) + (z + w));
        }
        PS[col][gs] = make_float4(p0, p1, p2, p3);
        __syncwarp();   // PS[*][gs] produced & consumed by the same 16 lanes

        // ---- PV + l: 4 rows x d-quad 'col'
        const float* vbase = VS[cur];
#pragma unroll
        for (int k2 = 0; k2 < 16; k2++) {
            ulonglong2 v2  = ((const ulonglong2*)(vbase + k2 * 68))[col];
            ulonglong2 pf2 = *((const ulonglong2*)&PS[k2][gs]);
            l01 = fma2(pf2.x, ONE2, l01);
            l23 = fma2(pf2.y, ONE2, l23);
            float pa, pb, pc, pd;
            upk2(pf2.x, pa, pb); upk2(pf2.y, pc, pd);
            ull pp0 = pk2(pa, pa), pp1 = pk2(pb, pb);
            ull pp2 = pk2(pc, pc), pp3 = pk2(pd, pd);
            oxy[0] = fma2(pp0, v2.x, oxy[0]); ozw[0] = fma2(pp0, v2.y, ozw[0]);
            oxy[1] = fma2(pp1, v2.x, oxy[1]); ozw[1] = fma2(pp1, v2.y, ozw[1]);
            oxy[2] = fma2(pp2, v2.x, oxy[2]); ozw[2] = fma2(pp2, v2.y, ozw[2]);
            oxy[3] = fma2(pp3, v2.x, oxy[3]); ozw[3] = fma2(pp3, v2.y, ozw[3]);
        }
        // top-of-loop __syncthreads orders these PV reads before iter b+1's PS store
    }

    // write unnormalized partials (rows gs*4+j)
#pragma unroll
    for (int j = 0; j < 4; j++) {
        float4 o;
        upk2(oxy[j], o.x, o.y); upk2(ozw[j], o.z, o.w);
        ((float4*)(g_po + ((h * NSPLIT + sp) * QLEN + gs * 4 + j) * HDIM))[col] = o;
    }
    if (col == 0) {
        float la, lb, lc, ld;
        upk2(l01, la, lb); upk2(l23, lc, ld);
        g_pl[(h * NSPLIT + sp) * QLEN + gs * 4 + 0] = la;
        g_pl[(h * NSPLIT + sp) * QLEN + gs * 4 + 1] = lb;
        g_pl[(h * NSPLIT + sp) * QLEN + gs * 4 + 2] = lc;
        g_pl[(h * NSPLIT + sp) * QLEN + gs * 4 + 3] = ld;
    }
}

// -----------------------------------------------------------------------------
// Kernel 3: additive combine over 128 splits, float4 + MLP=2.
// grid 128 (h,qi), 1024 threads.
// -----------------------------------------------------------------------------
__global__ __launch_bounds__(1024) void reduce_kernel() {
    int h = blockIdx.x >> 4, qi = blockIdx.x & 15, t = threadIdx.x;
    __shared__ float4 pacc[64][16];
    __shared__ float4 pacc2[16][16];
    __shared__ float  lpart[4];

    int q4 = t & 15, ch = t >> 4;   // 64 chunks of 2 splits
    const float4* src = (const float4*)g_po;
    float4 a0, a1;
    {
        long long base = ((long long)(h * NSPLIT + ch * 2) * QLEN + qi) * (HDIM / 4) + q4;
        const long long step = (long long)QLEN * (HDIM / 4);
        a0 = src[base];
        a1 = src[base + step];
    }
    float4 acc;
    acc.x = a0.x + a1.x; acc.y = a0.y + a1.y;
    acc.z = a0.z + a1.z; acc.w = a0.w + a1.w;
    pacc[ch][q4] = acc;

    if (t < NSPLIT) {
        float v = g_pl[(h * NSPLIT + t) * QLEN + qi];
#pragma unroll
        for (int off = 16; off; off >>= 1) v += __shfl_xor_sync(0xffffffffu, v, off);
        if ((t & 31) == 0) lpart[t >> 5] = v;
    }
    __syncthreads();

    if (t < 256) {
        int g = t >> 4;
        float4 s0 = pacc[g * 4 + 0][q4], s1 = pacc[g * 4 + 1][q4];
        float4 s2 = pacc[g * 4 + 2][q4], s3 = pacc[g * 4 + 3][q4];
        float4 s;
        s.x = (s0.x + s1.x) + (s2.x + s3.x);
        s.y = (s0.y + s1.y) + (s2.y + s3.y);
        s.z = (s0.z + s1.z) + (s2.z + s3.z);
        s.w = (s0.w + s1.w) + (s2.w + s3.w);
        pacc2[g][q4] = s;
    }
    __syncthreads();

    if (t < 16) {
        float4 s = make_float4(0.f, 0.f, 0.f, 0.f);
#pragma unroll
        for (int g = 0; g < 16; g++) {
            float4 v = pacc2[g][t];
            s.x += v.x; s.y += v.y; s.z += v.z; s.w += v.w;
        }
        float L = lpart[0] + lpart[1] + lpart[2] + lpart[3];
        float inv = 1.f / L;
        s.x *= inv; s.y *= inv; s.z *= inv; s.w *= inv;
        ((float4*)(g_ao + qi * HIDDEN + h * HDIM))[t] = s;
    }
}

// -----------------------------------------------------------------------------
// Kernel 4: out = g_ao @ Wo^T + bo (warp-per-output)
// -----------------------------------------------------------------------------
__global__ __launch_bounds__(256) void oproj_kernel(const float* __restrict__ Wo,
                                                    const float* __restrict__ bo,
                                                    float* __restrict__ out) {
    int gw   = (blockIdx.x * 256 + threadIdx.x) >> 5;
    int lane = threadIdx.x & 31;
    int s = gw >> 9;
    int j = gw & 511;
    const float4* x = (const float4*)(g_ao + s * HIDDEN);
    const float4* w = (const float4*)(Wo + j * HIDDEN);
    float acc = 0.f;
#pragma unroll
    for (int it = 0; it < 4; it++) {
        float4 a = x[lane + it * 32];
        float4 b = w[lane + it * 32];
        acc += a.x * b.x + a.y * b.y + a.z * b.z + a.w * b.w;
    }
#pragma unroll
    for (int off = 16; off; off >>= 1) acc += __shfl_xor_sync(0xffffffffu, acc, off);
    if (lane == 0) out[s * HIDDEN + j] = acc + bo[j];
}

// -----------------------------------------------------------------------------
extern "C" void kernel_launch(void* const* d_in, const int* in_sizes, int n_in,
                              void* d_out, int out_size) {
    const float *hs = 0, *kc = 0, *vc = 0, *Wq = 0, *bq = 0, *Wo = 0, *bo = 0;
    const int* bt_raw = 0;
    for (int i = 0; i < n_in; i++) {
        switch (in_sizes[i]) {
            case QLEN * HIDDEN:                 hs = (const float*)d_in[i]; break;
            case 4096 * NHEADS * BLKSZ * HDIM:
                if (!kc) kc = (const float*)d_in[i];
                else     vc = (const float*)d_in[i];
                break;
            case HIDDEN * HIDDEN:
                if (!Wq) Wq = (const float*)d_in[i];
                else     Wo = (const float*)d_in[i];
                break;
            case HIDDEN:
                if (!bq) bq = (const float*)d_in[i];
                else     bo = (const float*)d_in[i];
                break;
            case NLOGICAL:                      bt_raw = (const int*)d_in[i]; break;
            default: break;
        }
    }
    float* out = (float*)d_out;

    btnorm_kernel<<<1, 1024>>>(bt_raw);
    qproj_kernel<<<1024, 256>>>(hs, Wq, bq);
    dim3 g(NSPLIT, NHEADS);
    attn_kernel<<<g, 64>>>(kc, vc);
    reduce_kernel<<<NHEADS * QLEN, 1024>>>();
    oproj_kernel<<<1024, 256>>>(Wo, bo, out);
}

// round 10
// speedup vs baseline: 1.6190x; 1.1196x over previous
#include <cuda_runtime.h>
#include <cstdint>

#define NHEADS 8
#define HDIM   64
#define QLEN   16
#define HIDDEN 512
#define BLKSZ  16
#define NLOGICAL 2048
#define NSPLIT 128
#define BPS (NLOGICAL / NSPLIT)   // 16 blocks per split
#define ITERS (BPS / 2)           // 8 iterations of 32 keys

typedef unsigned long long ull;

// scratch (no cudaMalloc allowed)
__device__ __align__(16) float g_q [NHEADS * QLEN * HDIM];
__device__ __align__(16) float g_pl[NHEADS * NSPLIT * QLEN];
__device__ __align__(16) float g_po[NHEADS * NSPLIT * QLEN * HDIM];
__device__ __align__(16) float g_ao[QLEN * HIDDEN];
__device__ int g_bt[NLOGICAL];

// ---- packed f32x2 helpers --------------------------------------------------
__device__ __forceinline__ ull pk2(float lo, float hi) {
    ull r; asm("mov.b64 %0,{%1,%2};" : "=l"(r) : "f"(lo), "f"(hi)); return r;
}
__device__ __forceinline__ void upk2(ull p, float& lo, float& hi) {
    asm("mov.b64 {%0,%1},%2;" : "=f"(lo), "=f"(hi) : "l"(p));
}
__device__ __forceinline__ ull fma2(ull a, ull b, ull c) {
    ull d; asm("fma.rn.f32x2 %0,%1,%2,%3;" : "=l"(d) : "l"(a), "l"(b), "l"(c)); return d;
}

// ---- cp.async helpers --------------------------------------------------------
__device__ __forceinline__ uint32_t s2u(const void* p) {
    uint32_t a;
    asm("{ .reg .u64 t; cvta.to.shared.u64 t, %1; cvt.u32.u64 %0, t; }" : "=r"(a) : "l"(p));
    return a;
}
__device__ __forceinline__ void cpa16(uint32_t dst, const void* src) {
    asm volatile("cp.async.cg.shared.global [%0], [%1], 16;" :: "r"(dst), "l"(src) : "memory");
}
__device__ __forceinline__ void cpa_commit() {
    asm volatile("cp.async.commit_group;" ::: "memory");
}
__device__ __forceinline__ void cpa_wait0() {
    asm volatile("cp.async.wait_group 0;" ::: "memory");
}

// -----------------------------------------------------------------------------
// Kernel 1: q = (hs @ Wq^T + bq) * 0.125 -> g_q[h][s][d].
// CTA 1024 (extra) normalizes the block table instead (saves a launch; attn
// only reads g_bt after this kernel completes, by stream ordering).
// -----------------------------------------------------------------------------
__global__ __launch_bounds__(256) void qproj_kernel(const float* __restrict__ hs,
                                                    const float* __restrict__ Wq,
                                                    const float* __restrict__ bq,
                                                    const int* __restrict__ bt_raw) {
    if (blockIdx.x == 1024) {
        // ---- block-table normalization (int32 vs int64 LE auto-detect)
        __shared__ int s_odd_nonzero;
        if (threadIdx.x == 0) s_odd_nonzero = 0;
        __syncthreads();
        int t = threadIdx.x;
        int w[8];
        int flag = 0;
#pragma unroll
        for (int k = 0; k < 8; k++) {
            w[k] = bt_raw[t * 8 + k];
            if ((k & 1) && w[k] != 0) flag = 1;
        }
        if (flag) atomicOr(&s_odd_nonzero, 1);
        __syncthreads();
        bool is32 = (s_odd_nonzero != 0);
        if (is32) {
#pragma unroll
            for (int k = 0; k < 8; k++) g_bt[t * 8 + k] = w[k] & 4095;
        } else {
            // int64 LE: entry i at word 2i. Words 8t..8t+7 hold entries 4t..4t+3.
#pragma unroll
            for (int k = 0; k < 4; k++) g_bt[t * 4 + k] = w[2 * k] & 4095;
            // entries 1024..2047 live at words 2048..4094
#pragma unroll
            for (int k = 0; k < 4; k++)
                g_bt[1024 + t * 4 + k] = bt_raw[2048 + t * 8 + 2 * k] & 4095;
        }
        return;
    }

    int gw   = (blockIdx.x * 256 + threadIdx.x) >> 5;
    int lane = threadIdx.x & 31;
    int s = gw >> 9;
    int j = gw & 511;
    const float4* x = (const float4*)(hs + s * HIDDEN);
    const float4* w = (const float4*)(Wq + j * HIDDEN);
    float acc = 0.f;
#pragma unroll
    for (int it = 0; it < 4; it++) {
        float4 a = x[lane + it * 32];
        float4 b = w[lane + it * 32];
        acc += a.x * b.x + a.y * b.y + a.z * b.z + a.w * b.w;
    }
#pragma unroll
    for (int off = 16; off; off >>= 1) acc += __shfl_xor_sync(0xffffffffu, acc, off);
    if (lane == 0) {
        float v = (acc + bq[j]) * 0.125f;
        int h = j >> 6, d = j & 63;
        g_q[(h * QLEN + s) * HDIM + d] = v;
    }
}

// -----------------------------------------------------------------------------
// Kernel 2: split-KV attention. 64 threads, 4 q-rows/thread, 32-key tiles
// (2 KV blocks per iteration, 8 iterations). cp.async.cg staging; K padded-68,
// V linear. l accumulated in PV via packed fma2.
// grid (NSPLIT, NHEADS) = 1024 CTAs.
// -----------------------------------------------------------------------------
__global__ __launch_bounds__(64) void attn_kernel(const float* __restrict__ kc,
                                                  const float* __restrict__ vc) {
    const int h   = blockIdx.y;
    const int sp  = blockIdx.x;
    const int tid = threadIdx.x;
    const int col = tid & 15;
    const int gs  = tid >> 4;     // 0..3

    __shared__ __align__(16) float  QS[16 * 68];
    __shared__ __align__(16) float  KS[2][32 * 68];
    __shared__ __align__(16) float  VS[2][32 * 64];   // linear
    __shared__ __align__(16) float4 PS[32][4];        // [key][gs]

    // q tile -> smem
    {
        const float4* qg = (const float4*)(g_q + h * QLEN * HDIM);
#pragma unroll
        for (int j = 0; j < 4; j++) {
            int e = tid + j * 64;
            ((float4*)(QS + (e >> 4) * 68))[e & 15] = qg[e];
        }
    }

    uint32_t kbase0 = s2u(KS[0]), vbase0 = s2u(VS[0]);
    const uint32_t kstep = 32 * 68 * 4, vstep = 32 * 64 * 4;
    // K dst offsets (row = e>>4, chunk = e&15; stride 68 floats)
    uint32_t kdoff[8];
#pragma unroll
    for (int j = 0; j < 8; j++) {
        int e = tid + j * 64;
        kdoff[j] = (uint32_t)((e >> 4) * 68 * 4 + (e & 15) * 16);
    }

    const int lb0 = sp * BPS;
    const uint32_t headoff = (uint32_t)h * (BLKSZ * HDIM);

    // prologue: stage tile 0 (blocks lb0, lb0+1) into buffer 0
    {
        uint32_t b0 = (uint32_t)g_bt[lb0], b1 = (uint32_t)g_bt[lb0 + 1];
        const float* kb0 = kc + (size_t)b0 * (NHEADS * BLKSZ * HDIM) + headoff;
        const float* kb1 = kc + (size_t)b1 * (NHEADS * BLKSZ * HDIM) + headoff;
        const float* vb0 = vc + (size_t)b0 * (NHEADS * BLKSZ * HDIM) + headoff;
        const float* vb1 = vc + (size_t)b1 * (NHEADS * BLKSZ * HDIM) + headoff;
#pragma unroll
        for (int j = 0; j < 4; j++) {
            int e = tid + j * 64;
            cpa16(kbase0 + kdoff[j],     kb0 + e * 4);
            cpa16(kbase0 + kdoff[j + 4], kb1 + e * 4);
            cpa16(vbase0 + (uint32_t)e * 16,         vb0 + e * 4);
            cpa16(vbase0 + (uint32_t)(e + 256) * 16, vb1 + e * 4);
        }
        cpa_commit();
    }

    ull l01 = 0, l23 = 0;
    ull oxy[4] = {0, 0, 0, 0}, ozw[4] = {0, 0, 0, 0};
    const ull ONE2 = pk2(1.f, 1.f);

    const ulonglong2* qp0 = (const ulonglong2*)(QS + (gs * 4 + 0) * 68);
    const ulonglong2* qp1 = (const ulonglong2*)(QS + (gs * 4 + 1) * 68);
    const ulonglong2* qp2 = (const ulonglong2*)(QS + (gs * 4 + 2) * 68);
    const ulonglong2* qp3 = (const ulonglong2*)(QS + (gs * 4 + 3) * 68);

    for (int it = 0; it < ITERS; it++) {
        const int cur = it & 1;
        cpa_wait0();        // tile it landed in buffer cur
        __syncthreads();    // + everyone done reading buffer cur^1

        if (it + 1 < ITERS) {   // prefetch tile it+1 into the other buffer
            uint32_t b0 = (uint32_t)g_bt[lb0 + 2 * it + 2];
            uint32_t b1 = (uint32_t)g_bt[lb0 + 2 * it + 3];
            const float* kb0 = kc + (size_t)b0 * (NHEADS * BLKSZ * HDIM) + headoff;
            const float* kb1 = kc + (size_t)b1 * (NHEADS * BLKSZ * HDIM) + headoff;
            const float* vb0 = vc + (size_t)b0 * (NHEADS * BLKSZ * HDIM) + headoff;
            const float* vb1 = vc + (size_t)b1 * (NHEADS * BLKSZ * HDIM) + headoff;
            uint32_t kdst = kbase0 + (cur ^ 1) * kstep;
            uint32_t vdst = vbase0 + (cur ^ 1) * vstep;
#pragma unroll
            for (int j = 0; j < 4; j++) {
                int e = tid + j * 64;
                cpa16(kdst + kdoff[j],     kb0 + e * 4);
                cpa16(kdst + kdoff[j + 4], kb1 + e * 4);
                cpa16(vdst + (uint32_t)e * 16,         vb0 + e * 4);
                cpa16(vdst + (uint32_t)(e + 256) * 16, vb1 + e * 4);
            }
            cpa_commit();
        }

        // ---- scores: 4 rows x keys {col, col+16}
        const ulonglong2* kpA = (const ulonglong2*)(KS[cur] + col * 68);
        const ulonglong2* kpB = (const ulonglong2*)(KS[cur] + (col + 16) * 68);
        ull A0 = 0, B0 = 0, A1 = 0, B1 = 0, A2 = 0, B2 = 0, A3 = 0, B3 = 0;
        ull C0 = 0, D0 = 0, C1 = 0, D1 = 0, C2 = 0, D2 = 0, C3 = 0, D3 = 0;
#pragma unroll
        for (int i = 0; i < 16; i++) {
            ulonglong2 ka = kpA[i], kb = kpB[i];
            ulonglong2 q0 = qp0[i], q1 = qp1[i], q2 = qp2[i], q3 = qp3[i];
            A0 = fma2(q0.x, ka.x, A0); B0 = fma2(q0.y, ka.y, B0);
            A1 = fma2(q1.x, ka.x, A1); B1 = fma2(q1.y, ka.y, B1);
            A2 = fma2(q2.x, ka.x, A2); B2 = fma2(q2.y, ka.y, B2);
            A3 = fma2(q3.x, ka.x, A3); B3 = fma2(q3.y, ka.y, B3);
            C0 = fma2(q0.x, kb.x, C0); D0 = fma2(q0.y, kb.y, D0);
            C1 = fma2(q1.x, kb.x, C1); D1 = fma2(q1.y, kb.y, D1);
            C2 = fma2(q2.x, kb.x, C2); D2 = fma2(q2.y, kb.y, D2);
            C3 = fma2(q3.x, kb.x, C3); D3 = fma2(q3.y, kb.y, D3);
        }
        {
            float x, y, z, w;
            float pa0, pa1, pa2, pa3, pb0, pb1, pb2, pb3;
            upk2(A0, x, y); upk2(B0, z, w); pa0 = __expf((x + y) + (z + w));
            upk2(A1, x, y); upk2(B1, z, w); pa1 = __expf((x + y) + (z + w));
            upk2(A2, x, y); upk2(B2, z, w); pa2 = __expf((x + y) + (z + w));
            upk2(A3, x, y); upk2(B3, z, w); pa3 = __expf((x + y) + (z + w));
            upk2(C0, x, y); upk2(D0, z, w); pb0 = __expf((x + y) + (z + w));
            upk2(C1, x, y); upk2(D1, z, w); pb1 = __expf((x + y) + (z + w));
            upk2(C2, x, y); upk2(D2, z, w); pb2 = __expf((x + y) + (z + w));
            upk2(C3, x, y); upk2(D3, z, w); pb3 = __expf((x + y) + (z + w));
            PS[col][gs]      = make_float4(pa0, pa1, pa2, pa3);
            PS[col + 16][gs] = make_float4(pb0, pb1, pb2, pb3);
        }
        __syncwarp();   // PS[*][gs] produced & consumed by the same 16-lane groups

        // ---- PV + l: 4 rows x d-quad 'col', 32 keys
        const float* vbase = VS[cur];
#pragma unroll
        for (int k2 = 0; k2 < 32; k2++) {
            ulonglong2 v2  = ((const ulonglong2*)(vbase + k2 * 64))[col];
            ulonglong2 pf2 = *((const ulonglong2*)&PS[k2][gs]);
            l01 = fma2(pf2.x, ONE2, l01);
            l23 = fma2(pf2.y, ONE2, l23);
            float pa, pb, pc, pd;
            upk2(pf2.x, pa, pb); upk2(pf2.y, pc, pd);
            ull pp0 = pk2(pa, pa), pp1 = pk2(pb, pb);
            ull pp2 = pk2(pc, pc), pp3 = pk2(pd, pd);
            oxy[0] = fma2(pp0, v2.x, oxy[0]); ozw[0] = fma2(pp0, v2.y, ozw[0]);
            oxy[1] = fma2(pp1, v2.x, oxy[1]); ozw[1] = fma2(pp1, v2.y, ozw[1]);
            oxy[2] = fma2(pp2, v2.x, oxy[2]); ozw[2] = fma2(pp2, v2.y, ozw[2]);
            oxy[3] = fma2(pp3, v2.x, oxy[3]); ozw[3] = fma2(pp3, v2.y, ozw[3]);
        }
        // top-of-loop __syncthreads orders PV reads before next iter's PS stores
    }

    // write unnormalized partials (rows gs*4+j)
#pragma unroll
    for (int j = 0; j < 4; j++) {
        float4 o;
        upk2(oxy[j], o.x, o.y); upk2(ozw[j], o.z, o.w);
        ((float4*)(g_po + ((h * NSPLIT + sp) * QLEN + gs * 4 + j) * HDIM))[col] = o;
    }
    if (col == 0) {
        float la, lb, lc, ld;
        upk2(l01, la, lb); upk2(l23, lc, ld);
        g_pl[(h * NSPLIT + sp) * QLEN + gs * 4 + 0] = la;
        g_pl[(h * NSPLIT + sp) * QLEN + gs * 4 + 1] = lb;
        g_pl[(h * NSPLIT + sp) * QLEN + gs * 4 + 2] = lc;
        g_pl[(h * NSPLIT + sp) * QLEN + gs * 4 + 3] = ld;
    }
}

// -----------------------------------------------------------------------------
// Kernel 3: additive combine over 128 splits. grid 128 (h,qi), 1024 threads.
// -----------------------------------------------------------------------------
__global__ __launch_bounds__(1024) void reduce_kernel() {
    int h = blockIdx.x >> 4, qi = blockIdx.x & 15, t = threadIdx.x;
    __shared__ float4 pacc[64][16];
    __shared__ float4 pacc2[16][16];
    __shared__ float  lpart[4];

    int q4 = t & 15, ch = t >> 4;
    const float4* src = (const float4*)g_po;
    float4 a0, a1;
    {
        long long base = ((long long)(h * NSPLIT + ch * 2) * QLEN + qi) * (HDIM / 4) + q4;
        const long long step = (long long)QLEN * (HDIM / 4);
        a0 = src[base];
        a1 = src[base + step];
    }
    float4 acc;
    acc.x = a0.x + a1.x; acc.y = a0.y + a1.y;
    acc.z = a0.z + a1.z; acc.w = a0.w + a1.w;
    pacc[ch][q4] = acc;

    if (t < NSPLIT) {
        float v = g_pl[(h * NSPLIT + t) * QLEN + qi];
#pragma unroll
        for (int off = 16; off; off >>= 1) v += __shfl_xor_sync(0xffffffffu, v, off);
        if ((t & 31) == 0) lpart[t >> 5] = v;
    }
    __syncthreads();

    if (t < 256) {
        int g = t >> 4;
        float4 s0 = pacc[g * 4 + 0][q4], s1 = pacc[g * 4 + 1][q4];
        float4 s2 = pacc[g * 4 + 2][q4], s3 = pacc[g * 4 + 3][q4];
        float4 s;
        s.x = (s0.x + s1.x) + (s2.x + s3.x);
        s.y = (s0.y + s1.y) + (s2.y + s3.y);
        s.z = (s0.z + s1.z) + (s2.z + s3.z);
        s.w = (s0.w + s1.w) + (s2.w + s3.w);
        pacc2[g][q4] = s;
    }
    __syncthreads();

    if (t < 16) {
        float4 s = make_float4(0.f, 0.f, 0.f, 0.f);
#pragma unroll
        for (int g = 0; g < 16; g++) {
            float4 v = pacc2[g][t];
            s.x += v.x; s.y += v.y; s.z += v.z; s.w += v.w;
        }
        float L = lpart[0] + lpart[1] + lpart[2] + lpart[3];
        float inv = 1.f / L;
        s.x *= inv; s.y *= inv; s.z *= inv; s.w *= inv;
        ((float4*)(g_ao + qi * HIDDEN + h * HDIM))[t] = s;
    }
}

// -----------------------------------------------------------------------------
// Kernel 4: out = g_ao @ Wo^T + bo (warp-per-output)
// -----------------------------------------------------------------------------
__global__ __launch_bounds__(256) void oproj_kernel(const float* __restrict__ Wo,
                                                    const float* __restrict__ bo,
                                                    float* __restrict__ out) {
    int gw   = (blockIdx.x * 256 + threadIdx.x) >> 5;
    int lane = threadIdx.x & 31;
    int s = gw >> 9;
    int j = gw & 511;
    const float4* x = (const float4*)(g_ao + s * HIDDEN);
    const float4* w = (const float4*)(Wo + j * HIDDEN);
    float acc = 0.f;
#pragma unroll
    for (int it = 0; it < 4; it++) {
        float4 a = x[lane + it * 32];
        float4 b = w[lane + it * 32];
        acc += a.x * b.x + a.y * b.y + a.z * b.z + a.w * b.w;
    }
#pragma unroll
    for (int off = 16; off; off >>= 1) acc += __shfl_xor_sync(0xffffffffu, acc, off);
    if (lane == 0) out[s * HIDDEN + j] = acc + bo[j];
}

// -----------------------------------------------------------------------------
extern "C" void kernel_launch(void* const* d_in, const int* in_sizes, int n_in,
                              void* d_out, int out_size) {
    const float *hs = 0, *kc = 0, *vc = 0, *Wq = 0, *bq = 0, *Wo = 0, *bo = 0;
    const int* bt_raw = 0;
    for (int i = 0; i < n_in; i++) {
        switch (in_sizes[i]) {
            case QLEN * HIDDEN:                 hs = (const float*)d_in[i]; break;
            case 4096 * NHEADS * BLKSZ * HDIM:
                if (!kc) kc = (const float*)d_in[i];
                else     vc = (const float*)d_in[i];
                break;
            case HIDDEN * HIDDEN:
                if (!Wq) Wq = (const float*)d_in[i];
                else     Wo = (const float*)d_in[i];
                break;
            case HIDDEN:
                if (!bq) bq = (const float*)d_in[i];
                else     bo = (const float*)d_in[i];
                break;
            case NLOGICAL:                      bt_raw = (const int*)d_in[i]; break;
            default: break;
        }
    }
    float* out = (float*)d_out;

    qproj_kernel<<<1025, 256>>>(hs, Wq, bq, bt_raw);  // CTA 1024 = btnorm
    dim3 g(NSPLIT, NHEADS);
    attn_kernel<<<g, 64>>>(kc, vc);
    reduce_kernel<<<NHEADS * QLEN, 1024>>>();
    oproj_kernel<<<1024, 256>>>(Wo, bo, out);
}

// round 11
// speedup vs baseline: 1.6260x; 1.0043x over previous
#include <cuda_runtime.h>
#include <cstdint>

#define NHEADS 8
#define HDIM   64
#define QLEN   16
#define HIDDEN 512
#define BLKSZ  16
#define NLOGICAL 2048
#define NSPLIT 128
#define BPS (NLOGICAL / NSPLIT)   // 16 blocks per split
#define ITERS (BPS / 2)           // 8 iterations of 32 keys

typedef unsigned long long ull;

// scratch (no cudaMalloc allowed)
__device__ __align__(16) float g_q [NHEADS * QLEN * HDIM];
__device__ __align__(16) float g_pl[NHEADS * NSPLIT * QLEN];
__device__ __align__(16) float g_po[NHEADS * NSPLIT * QLEN * HDIM];
__device__ __align__(16) float g_ao[QLEN * HIDDEN];
__device__ int g_bt[NLOGICAL];
__device__ int g_cnt;            // reduce->oproj barrier (reset by qproj each replay)

// ---- packed f32x2 helpers --------------------------------------------------
__device__ __forceinline__ ull pk2(float lo, float hi) {
    ull r; asm("mov.b64 %0,{%1,%2};" : "=l"(r) : "f"(lo), "f"(hi)); return r;
}
__device__ __forceinline__ void upk2(ull p, float& lo, float& hi) {
    asm("mov.b64 {%0,%1},%2;" : "=f"(lo), "=f"(hi) : "l"(p));
}
__device__ __forceinline__ ull fma2(ull a, ull b, ull c) {
    ull d; asm("fma.rn.f32x2 %0,%1,%2,%3;" : "=l"(d) : "l"(a), "l"(b), "l"(c)); return d;
}

// ---- cp.async helpers --------------------------------------------------------
__device__ __forceinline__ uint32_t s2u(const void* p) {
    uint32_t a;
    asm("{ .reg .u64 t; cvta.to.shared.u64 t, %1; cvt.u32.u64 %0, t; }" : "=r"(a) : "l"(p));
    return a;
}
__device__ __forceinline__ void cpa16(uint32_t dst, const void* src) {
    asm volatile("cp.async.cg.shared.global [%0], [%1], 16;" :: "r"(dst), "l"(src) : "memory");
}
__device__ __forceinline__ void cpa_commit() {
    asm volatile("cp.async.commit_group;" ::: "memory");
}
__device__ __forceinline__ void cpa_wait0() {
    asm volatile("cp.async.wait_group 0;" ::: "memory");
}

// -----------------------------------------------------------------------------
// Kernel 1: q = (hs @ Wq^T + bq) * 0.125 -> g_q[h][s][d].
// CTA 1024 normalizes the block table and resets the fused-kernel barrier.
// -----------------------------------------------------------------------------
__global__ __launch_bounds__(256) void qproj_kernel(const float* __restrict__ hs,
                                                    const float* __restrict__ Wq,
                                                    const float* __restrict__ bq,
                                                    const int* __restrict__ bt_raw) {
    if (blockIdx.x == 1024) {
        if (threadIdx.x == 0) g_cnt = 0;   // reset spin barrier for this replay
        __shared__ int s_odd_nonzero;
        if (threadIdx.x == 0) s_odd_nonzero = 0;
        __syncthreads();
        int t = threadIdx.x;
        int w[8];
        int flag = 0;
#pragma unroll
        for (int k = 0; k < 8; k++) {
            w[k] = bt_raw[t * 8 + k];
            if ((k & 1) && w[k] != 0) flag = 1;
        }
        if (flag) atomicOr(&s_odd_nonzero, 1);
        __syncthreads();
        bool is32 = (s_odd_nonzero != 0);
        if (is32) {
#pragma unroll
            for (int k = 0; k < 8; k++) g_bt[t * 8 + k] = w[k] & 4095;
        } else {
#pragma unroll
            for (int k = 0; k < 4; k++) g_bt[t * 4 + k] = w[2 * k] & 4095;
#pragma unroll
            for (int k = 0; k < 4; k++)
                g_bt[1024 + t * 4 + k] = bt_raw[2048 + t * 8 + 2 * k] & 4095;
        }
        return;
    }

    int gw   = (blockIdx.x * 256 + threadIdx.x) >> 5;
    int lane = threadIdx.x & 31;
    int s = gw >> 9;
    int j = gw & 511;
    const float4* x = (const float4*)(hs + s * HIDDEN);
    const float4* w = (const float4*)(Wq + j * HIDDEN);
    float acc = 0.f;
#pragma unroll
    for (int it = 0; it < 4; it++) {
        float4 a = x[lane + it * 32];
        float4 b = w[lane + it * 32];
        acc += a.x * b.x + a.y * b.y + a.z * b.z + a.w * b.w;
    }
#pragma unroll
    for (int off = 16; off; off >>= 1) acc += __shfl_xor_sync(0xffffffffu, acc, off);
    if (lane == 0) {
        float v = (acc + bq[j]) * 0.125f;
        int h = j >> 6, d = j & 63;
        g_q[(h * QLEN + s) * HDIM + d] = v;
    }
}

// -----------------------------------------------------------------------------
// Kernel 2: split-KV attention (unchanged from R10 winner).
// -----------------------------------------------------------------------------
__global__ __launch_bounds__(64) void attn_kernel(const float* __restrict__ kc,
                                                  const float* __restrict__ vc) {
    const int h   = blockIdx.y;
    const int sp  = blockIdx.x;
    const int tid = threadIdx.x;
    const int col = tid & 15;
    const int gs  = tid >> 4;

    __shared__ __align__(16) float  QS[16 * 68];
    __shared__ __align__(16) float  KS[2][32 * 68];
    __shared__ __align__(16) float  VS[2][32 * 64];
    __shared__ __align__(16) float4 PS[32][4];

    {
        const float4* qg = (const float4*)(g_q + h * QLEN * HDIM);
#pragma unroll
        for (int j = 0; j < 4; j++) {
            int e = tid + j * 64;
            ((float4*)(QS + (e >> 4) * 68))[e & 15] = qg[e];
        }
    }

    uint32_t kbase0 = s2u(KS[0]), vbase0 = s2u(VS[0]);
    const uint32_t kstep = 32 * 68 * 4, vstep = 32 * 64 * 4;
    uint32_t kdoff[8];
#pragma unroll
    for (int j = 0; j < 8; j++) {
        int e = tid + j * 64;
        kdoff[j] = (uint32_t)((e >> 4) * 68 * 4 + (e & 15) * 16);
    }

    const int lb0 = sp * BPS;
    const uint32_t headoff = (uint32_t)h * (BLKSZ * HDIM);

    {
        uint32_t b0 = (uint32_t)g_bt[lb0], b1 = (uint32_t)g_bt[lb0 + 1];
        const float* kb0 = kc + (size_t)b0 * (NHEADS * BLKSZ * HDIM) + headoff;
        const float* kb1 = kc + (size_t)b1 * (NHEADS * BLKSZ * HDIM) + headoff;
        const float* vb0 = vc + (size_t)b0 * (NHEADS * BLKSZ * HDIM) + headoff;
        const float* vb1 = vc + (size_t)b1 * (NHEADS * BLKSZ * HDIM) + headoff;
#pragma unroll
        for (int j = 0; j < 4; j++) {
            int e = tid + j * 64;
            cpa16(kbase0 + kdoff[j],     kb0 + e * 4);
            cpa16(kbase0 + kdoff[j + 4], kb1 + e * 4);
            cpa16(vbase0 + (uint32_t)e * 16,         vb0 + e * 4);
            cpa16(vbase0 + (uint32_t)(e + 256) * 16, vb1 + e * 4);
        }
        cpa_commit();
    }

    ull l01 = 0, l23 = 0;
    ull oxy[4] = {0, 0, 0, 0}, ozw[4] = {0, 0, 0, 0};
    const ull ONE2 = pk2(1.f, 1.f);

    const ulonglong2* qp0 = (const ulonglong2*)(QS + (gs * 4 + 0) * 68);
    const ulonglong2* qp1 = (const ulonglong2*)(QS + (gs * 4 + 1) * 68);
    const ulonglong2* qp2 = (const ulonglong2*)(QS + (gs * 4 + 2) * 68);
    const ulonglong2* qp3 = (const ulonglong2*)(QS + (gs * 4 + 3) * 68);

    for (int it = 0; it < ITERS; it++) {
        const int cur = it & 1;
        cpa_wait0();
        __syncthreads();

        if (it + 1 < ITERS) {
            uint32_t b0 = (uint32_t)g_bt[lb0 + 2 * it + 2];
            uint32_t b1 = (uint32_t)g_bt[lb0 + 2 * it + 3];
            const float* kb0 = kc + (size_t)b0 * (NHEADS * BLKSZ * HDIM) + headoff;
            const float* kb1 = kc + (size_t)b1 * (NHEADS * BLKSZ * HDIM) + headoff;
            const float* vb0 = vc + (size_t)b0 * (NHEADS * BLKSZ * HDIM) + headoff;
            const float* vb1 = vc + (size_t)b1 * (NHEADS * BLKSZ * HDIM) + headoff;
            uint32_t kdst = kbase0 + (cur ^ 1) * kstep;
            uint32_t vdst = vbase0 + (cur ^ 1) * vstep;
#pragma unroll
            for (int j = 0; j < 4; j++) {
                int e = tid + j * 64;
                cpa16(kdst + kdoff[j],     kb0 + e * 4);
                cpa16(kdst + kdoff[j + 4], kb1 + e * 4);
                cpa16(vdst + (uint32_t)e * 16,         vb0 + e * 4);
                cpa16(vdst + (uint32_t)(e + 256) * 16, vb1 + e * 4);
            }
            cpa_commit();
        }

        const ulonglong2* kpA = (const ulonglong2*)(KS[cur] + col * 68);
        const ulonglong2* kpB = (const ulonglong2*)(KS[cur] + (col + 16) * 68);
        ull A0 = 0, B0 = 0, A1 = 0, B1 = 0, A2 = 0, B2 = 0, A3 = 0, B3 = 0;
        ull C0 = 0, D0 = 0, C1 = 0, D1 = 0, C2 = 0, D2 = 0, C3 = 0, D3 = 0;
#pragma unroll
        for (int i = 0; i < 16; i++) {
            ulonglong2 ka = kpA[i], kb = kpB[i];
            ulonglong2 q0 = qp0[i], q1 = qp1[i], q2 = qp2[i], q3 = qp3[i];
            A0 = fma2(q0.x, ka.x, A0); B0 = fma2(q0.y, ka.y, B0);
            A1 = fma2(q1.x, ka.x, A1); B1 = fma2(q1.y, ka.y, B1);
            A2 = fma2(q2.x, ka.x, A2); B2 = fma2(q2.y, ka.y, B2);
            A3 = fma2(q3.x, ka.x, A3); B3 = fma2(q3.y, ka.y, B3);
            C0 = fma2(q0.x, kb.x, C0); D0 = fma2(q0.y, kb.y, D0);
            C1 = fma2(q1.x, kb.x, C1); D1 = fma2(q1.y, kb.y, D1);
            C2 = fma2(q2.x, kb.x, C2); D2 = fma2(q2.y, kb.y, D2);
            C3 = fma2(q3.x, kb.x, C3); D3 = fma2(q3.y, kb.y, D3);
        }
        {
            float x, y, z, w;
            float pa0, pa1, pa2, pa3, pb0, pb1, pb2, pb3;
            upk2(A0, x, y); upk2(B0, z, w); pa0 = __expf((x + y) + (z + w));
            upk2(A1, x, y); upk2(B1, z, w); pa1 = __expf((x + y) + (z + w));
            upk2(A2, x, y); upk2(B2, z, w); pa2 = __expf((x + y) + (z + w));
            upk2(A3, x, y); upk2(B3, z, w); pa3 = __expf((x + y) + (z + w));
            upk2(C0, x, y); upk2(D0, z, w); pb0 = __expf((x + y) + (z + w));
            upk2(C1, x, y); upk2(D1, z, w); pb1 = __expf((x + y) + (z + w));
            upk2(C2, x, y); upk2(D2, z, w); pb2 = __expf((x + y) + (z + w));
            upk2(C3, x, y); upk2(D3, z, w); pb3 = __expf((x + y) + (z + w));
            PS[col][gs]      = make_float4(pa0, pa1, pa2, pa3);
            PS[col + 16][gs] = make_float4(pb0, pb1, pb2, pb3);
        }
        __syncwarp();

        const float* vbase = VS[cur];
#pragma unroll
        for (int k2 = 0; k2 < 32; k2++) {
            ulonglong2 v2  = ((const ulonglong2*)(vbase + k2 * 64))[col];
            ulonglong2 pf2 = *((const ulonglong2*)&PS[k2][gs]);
            l01 = fma2(pf2.x, ONE2, l01);
            l23 = fma2(pf2.y, ONE2, l23);
            float pa, pb, pc, pd;
            upk2(pf2.x, pa, pb); upk2(pf2.y, pc, pd);
            ull pp0 = pk2(pa, pa), pp1 = pk2(pb, pb);
            ull pp2 = pk2(pc, pc), pp3 = pk2(pd, pd);
            oxy[0] = fma2(pp0, v2.x, oxy[0]); ozw[0] = fma2(pp0, v2.y, ozw[0]);
            oxy[1] = fma2(pp1, v2.x, oxy[1]); ozw[1] = fma2(pp1, v2.y, ozw[1]);
            oxy[2] = fma2(pp2, v2.x, oxy[2]); ozw[2] = fma2(pp2, v2.y, ozw[2]);
            oxy[3] = fma2(pp3, v2.x, oxy[3]); ozw[3] = fma2(pp3, v2.y, ozw[3]);
        }
    }

#pragma unroll
    for (int j = 0; j < 4; j++) {
        float4 o;
        upk2(oxy[j], o.x, o.y); upk2(ozw[j], o.z, o.w);
        ((float4*)(g_po + ((h * NSPLIT + sp) * QLEN + gs * 4 + j) * HDIM))[col] = o;
    }
    if (col == 0) {
        float la, lb, lc, ld;
        upk2(l01, la, lb); upk2(l23, lc, ld);
        g_pl[(h * NSPLIT + sp) * QLEN + gs * 4 + 0] = la;
        g_pl[(h * NSPLIT + sp) * QLEN + gs * 4 + 1] = lb;
        g_pl[(h * NSPLIT + sp) * QLEN + gs * 4 + 2] = lc;
        g_pl[(h * NSPLIT + sp) * QLEN + gs * 4 + 3] = ld;
    }
}

// -----------------------------------------------------------------------------
// Kernel 3 (fused): reduce over 128 splits + out-projection.
// 128 CTAs (single wave, <=148 SMs) x 1024 threads.
//   Stage 0: prefetch this CTA's 4 Wo rows into smem via cp.async (hidden
//            behind stage 1).
//   Stage 1: reduce g_po -> g_ao slice (h = bid>>4, qi = bid&15).
//   Barrier: global atomic counter (reset by qproj each replay).
//   Stage 2: load full g_ao to smem; 64 outputs (16 s x 4 j), warp-per-output.
// -----------------------------------------------------------------------------
__global__ __launch_bounds__(1024) void fused_tail_kernel(const float* __restrict__ Wo,
                                                          const float* __restrict__ bo,
                                                          float* __restrict__ out) {
    const int bid = blockIdx.x;
    const int h = bid >> 4, qi = bid & 15;
    const int t = threadIdx.x;
    const int jbase = bid * 4;    // this CTA's 4 output columns

    __shared__ float4 pacc[64][16];
    __shared__ float4 pacc2[16][16];
    __shared__ float  lpart[4];
    __shared__ __align__(16) float WS[4][HIDDEN];   // 8 KB: Wo rows jbase..jbase+3
    __shared__ __align__(16) float AS[QLEN * HIDDEN]; // 32 KB: full g_ao

    // ---- stage 0: prefetch Wo rows (async; consumed in stage 2)
    if (t < 512) {
        int row = t >> 7, chunk = t & 127;   // 128 x 16B per row
        cpa16(s2u(&WS[row][chunk * 4]), Wo + (size_t)(jbase + row) * HIDDEN + chunk * 4);
    }
    cpa_commit();

    // ---- stage 1: reduce (identical math to previous reduce_kernel)
    int q4 = t & 15, ch = t >> 4;
    const float4* src = (const float4*)g_po;
    float4 a0, a1;
    {
        long long base = ((long long)(h * NSPLIT + ch * 2) * QLEN + qi) * (HDIM / 4) + q4;
        const long long step = (long long)QLEN * (HDIM / 4);
        a0 = src[base];
        a1 = src[base + step];
    }
    float4 acc;
    acc.x = a0.x + a1.x; acc.y = a0.y + a1.y;
    acc.z = a0.z + a1.z; acc.w = a0.w + a1.w;
    pacc[ch][q4] = acc;

    if (t < NSPLIT) {
        float v = g_pl[(h * NSPLIT + t) * QLEN + qi];
#pragma unroll
        for (int off = 16; off; off >>= 1) v += __shfl_xor_sync(0xffffffffu, v, off);
        if ((t & 31) == 0) lpart[t >> 5] = v;
    }
    __syncthreads();

    if (t < 256) {
        int g = t >> 4;
        float4 s0 = pacc[g * 4 + 0][q4], s1 = pacc[g * 4 + 1][q4];
        float4 s2 = pacc[g * 4 + 2][q4], s3 = pacc[g * 4 + 3][q4];
        float4 s;
        s.x = (s0.x + s1.x) + (s2.x + s3.x);
        s.y = (s0.y + s1.y) + (s2.y + s3.y);
        s.z = (s0.z + s1.z) + (s2.z + s3.z);
        s.w = (s0.w + s1.w) + (s2.w + s3.w);
        pacc2[g][q4] = s;
    }
    __syncthreads();

    if (t < 16) {
        float4 s = make_float4(0.f, 0.f, 0.f, 0.f);
#pragma unroll
        for (int g = 0; g < 16; g++) {
            float4 v = pacc2[g][t];
            s.x += v.x; s.y += v.y; s.z += v.z; s.w += v.w;
        }
        float L = lpart[0] + lpart[1] + lpart[2] + lpart[3];
        float inv = 1.f / L;
        s.x *= inv; s.y *= inv; s.z *= inv; s.w *= inv;
        ((float4*)(g_ao + qi * HIDDEN + h * HDIM))[t] = s;
    }
    __syncthreads();

    // ---- global barrier: all 128 CTAs have published their g_ao slice
    if (t == 0) {
        __threadfence();
        atomicAdd(&g_cnt, 1);
        while (atomicAdd(&g_cnt, 0) < 128) { __nanosleep(64); }
    }
    __syncthreads();
    __threadfence();

    // ---- stage 2: load full g_ao, compute 64 outputs (warp-per-output)
    {
        const float4* ag = (const float4*)g_ao;
        float4* asp = (float4*)AS;
#pragma unroll
        for (int j = 0; j < 2; j++) asp[t + j * 1024] = ag[t + j * 1024];
    }
    cpa_wait0();       // WS ready
    __syncthreads();

    int w = t >> 5, lane = t & 31;
#pragma unroll
    for (int r = 0; r < 2; r++) {
        int o  = r * 32 + w;       // 0..63
        int s  = o & 15;
        int jj = o >> 4;           // 0..3
        const float4* x = (const float4*)(AS + s * HIDDEN);
        const float4* ww = (const float4*)(WS[jj]);
        float acc2 = 0.f;
#pragma unroll
        for (int it = 0; it < 4; it++) {
            float4 a = x[lane + it * 32];
            float4 b = ww[lane + it * 32];
            acc2 += a.x * b.x + a.y * b.y + a.z * b.z + a.w * b.w;
        }
#pragma unroll
        for (int off = 16; off; off >>= 1) acc2 += __shfl_xor_sync(0xffffffffu, acc2, off);
        if (lane == 0) out[s * HIDDEN + jbase + jj] = acc2 + bo[jbase + jj];
    }
}

// -----------------------------------------------------------------------------
extern "C" void kernel_launch(void* const* d_in, const int* in_sizes, int n_in,
                              void* d_out, int out_size) {
    const float *hs = 0, *kc = 0, *vc = 0, *Wq = 0, *bq = 0, *Wo = 0, *bo = 0;
    const int* bt_raw = 0;
    for (int i = 0; i < n_in; i++) {
        switch (in_sizes[i]) {
            case QLEN * HIDDEN:                 hs = (const float*)d_in[i]; break;
            case 4096 * NHEADS * BLKSZ * HDIM:
                if (!kc) kc = (const float*)d_in[i];
                else     vc = (const float*)d_in[i];
                break;
            case HIDDEN * HIDDEN:
                if (!Wq) Wq = (const float*)d_in[i];
                else     Wo = (const float*)d_in[i];
                break;
            case HIDDEN:
                if (!bq) bq = (const float*)d_in[i];
                else     bo = (const float*)d_in[i];
                break;
            case NLOGICAL:                      bt_raw = (const int*)d_in[i]; break;
            default: break;
        }
    }
    float* out = (float*)d_out;

    qproj_kernel<<<1025, 256>>>(hs, Wq, bq, bt_raw);  // CTA 1024 = btnorm + barrier reset
    dim3 g(NSPLIT, NHEADS);
    attn_kernel<<<g, 64>>>(kc, vc);
    fused_tail_kernel<<<128, 1024>>>(Wo, bo, out);
}